// round 7
// baseline (speedup 1.0000x reference)
#include <cuda_runtime.h>
#include <cuda_bf16.h>
#include <stdint.h>

#define NHEAD 8
#define SLEN 2048
#define NSPLIT 4
#define SCALE 0.17677669529663689f
#define LOG2E 1.4426950408889634f

// ------------- device scratch (no allocation allowed) -------------
static __device__ __align__(16) __nv_bfloat16 g_Qhi[NHEAD][SLEN][32], g_Qlo[NHEAD][SLEN][32];
static __device__ __align__(16) __nv_bfloat16 g_Khi[NHEAD][SLEN][32], g_Klo[NHEAD][SLEN][32];
static __device__ __align__(16) __nv_bfloat16 g_Vthi[NHEAD][32][SLEN], g_Vtlo[NHEAD][32][SLEN];
static __device__ __align__(16) float g_G[NHEAD][SLEN][32];
static __device__ __align__(16) float g_AO[SLEN][256];
// split-K partials: unnormalized O, plus (m, l) per row
static __device__ __align__(16) float g_Opart[NSPLIT][NHEAD][SLEN][32];
static __device__ __align__(16) float g_ml[NSPLIT][NHEAD][SLEN][2];

// ------------- helpers -------------
__device__ __forceinline__ unsigned long long dup2(float x) {
    unsigned long long r; asm("mov.b64 %0, {%1,%1};" : "=l"(r) : "f"(x)); return r;
}
__device__ __forceinline__ unsigned long long pk2(float2 v) {
    unsigned long long r; asm("mov.b64 %0, {%1,%2};" : "=l"(r) : "f"(v.x), "f"(v.y)); return r;
}
__device__ __forceinline__ void fma2(unsigned long long &d, unsigned long long a, unsigned long long b) {
    asm("fma.rn.f32x2 %0, %1, %2, %0;" : "+l"(d) : "l"(a), "l"(b));
}
__device__ __forceinline__ float2 unpack2(unsigned long long v) {
    float2 r; asm("mov.b64 {%0,%1}, %2;" : "=f"(r.x), "=f"(r.y) : "l"(v)); return r;
}
__device__ __forceinline__ float ex2f(float x) {
    float y; asm("ex2.approx.f32 %0, %1;" : "=f"(y) : "f"(x)); return y;
}
__device__ __forceinline__ uint32_t packbf(float lo, float hi) {
    uint32_t r; asm("cvt.rn.bf16x2.f32 %0, %1, %2;" : "=r"(r) : "f"(hi), "f"(lo)); return r;
}
__device__ __forceinline__ void splitp(float x, float y, uint32_t &hi, uint32_t &lo) {
    hi = packbf(x, y);
    float xh = __uint_as_float(hi << 16);
    float yh = __uint_as_float(hi & 0xffff0000u);
    lo = packbf(x - xh, y - yh);
}
__device__ __forceinline__ void mma_bf16(float* d, const uint32_t* a, uint32_t b0, uint32_t b1) {
    asm volatile("mma.sync.aligned.m16n8k16.row.col.f32.bf16.bf16.f32 "
        "{%0,%1,%2,%3},{%4,%5,%6,%7},{%8,%9},{%0,%1,%2,%3};"
        : "+f"(d[0]), "+f"(d[1]), "+f"(d[2]), "+f"(d[3])
        : "r"(a[0]), "r"(a[1]), "r"(a[2]), "r"(a[3]), "r"(b0), "r"(b1));
}
__device__ __forceinline__ uint32_t smaddr(const void* p) {
    return (uint32_t)__cvta_generic_to_shared(p);
}
__device__ __forceinline__ void cp_async16(uint32_t s, const void* g) {
    asm volatile("cp.async.cg.shared.global [%0], [%1], 16;" :: "r"(s), "l"(g));
}
__device__ __forceinline__ void cp_commit() { asm volatile("cp.async.commit_group;"); }
template<int N> __device__ __forceinline__ void cp_wait() {
    asm volatile("cp.async.wait_group %0;" :: "n"(N));
}

// =============== kernel 1: input projections (fp32 f32x2, double-buffered) ===============
__global__ __launch_bounds__(128) void proj_kernel(
    const float* __restrict__ Xq, const float* __restrict__ Xkv,
    const float* __restrict__ Wq, const float* __restrict__ Wk,
    const float* __restrict__ Bq, const float* __restrict__ Bk)
{
    __shared__ __align__(16) float As[2][64][20];
    __shared__ __align__(16) float Bs[2][16][64];
    const int z = blockIdx.z;
    const float* __restrict__ X  = z ? Xkv : Xq;
    const float* __restrict__ W  = z ? Wk  : Wq;
    const float* __restrict__ Bv = z ? Bk  : Bq;
    const int m0 = blockIdx.y * 64, n0b = blockIdx.x * 64;
    const int tid = threadIdx.x, tx = tid & 15, ty = tid >> 4;

    unsigned long long acc[8][2];
#pragma unroll
    for (int i = 0; i < 8; i++) { acc[i][0] = 0ull; acc[i][1] = 0ull; }

    auto load_stage = [&](int s, int kt) {
#pragma unroll
        for (int p = 0; p < 2; p++) {
            int e = tid + p * 128, r = e >> 2, kq = e & 3;
            cp_async16(smaddr(&As[s][r][kq * 4]), &X[(m0 + r) * 256 + kt + kq * 4]);
        }
#pragma unroll
        for (int p = 0; p < 2; p++) {
            int e = tid + p * 128, k = e >> 4, nq = e & 15;
            cp_async16(smaddr(&Bs[s][k][nq * 4]), &W[(kt + k) * 512 + n0b + nq * 4]);
        }
    };

    load_stage(0, 0); cp_commit();

    for (int it = 0; it < 16; it++) {
        const int buf = it & 1;
        cp_wait<0>();
        __syncthreads();
        if (it + 1 < 16) { load_stage(buf ^ 1, (it + 1) * 16); cp_commit(); }
#pragma unroll
        for (int k = 0; k < 16; k++) {
            unsigned long long b0 = pk2(*(const float2*)&Bs[buf][k][tx * 4]);
            unsigned long long b1 = pk2(*(const float2*)&Bs[buf][k][tx * 4 + 2]);
#pragma unroll
            for (int i = 0; i < 8; i++) {
                unsigned long long a = dup2(As[buf][ty * 8 + i][k]);
                fma2(acc[i][0], a, b0);
                fma2(acc[i][1], a, b1);
            }
        }
        __syncthreads();
    }
#pragma unroll
    for (int i = 0; i < 8; i++) {
        int q = m0 + ty * 8 + i;
#pragma unroll
        for (int j = 0; j < 2; j++) {
            float2 v = unpack2(acc[i][j]);
            float vv[2] = { v.x, v.y };
#pragma unroll
            for (int e = 0; e < 2; e++) {
                int col = n0b + tx * 4 + j * 2 + e;
                int h = col >> 6, cc = col & 63;
                float x = vv[e] + Bv[col];
                if (z == 0) {
                    if (cc < 32) {
                        float s = x * SCALE;
                        __nv_bfloat16 hi = __float2bfloat16(s);
                        g_Qhi[h][q][cc] = hi;
                        g_Qlo[h][q][cc] = __float2bfloat16(s - __bfloat162float(hi));
                    } else {
                        g_G[h][q][cc - 32] = 1.0f / (1.0f + __expf(-x));
                    }
                } else {
                    __nv_bfloat16 hi = __float2bfloat16(x);
                    float lo = x - __bfloat162float(hi);
                    if (cc < 32) {
                        g_Khi[h][q][cc] = hi; g_Klo[h][q][cc] = __float2bfloat16(lo);
                    } else {
                        g_Vthi[h][cc - 32][q] = hi; g_Vtlo[h][cc - 32][q] = __float2bfloat16(lo);
                    }
                }
            }
        }
    }
}

// =============== kernel 2: flash attention, split-K x4 (split-bf16 MMA) ===============
// blockIdx.z = k-quarter: this block processes k-tiles (4*it + z)*64, it in [0,8)
__global__ __launch_bounds__(128) void attn_kernel(const float* __restrict__ bias)
{
    __shared__ __align__(16) __nv_bfloat16 Kh[2][64][40], Kl[2][64][40];
    __shared__ __align__(16) __nv_bfloat16 Vh[2][32][72], Vl[2][32][72];
    const int h = blockIdx.y;
    const int z = blockIdx.z;
    const int tid = threadIdx.x, wid = tid >> 5, ln = tid & 31;
    const int q0 = blockIdx.x * 64 + wid * 16;
    const int r0 = ln >> 2, c0 = (ln & 3) * 2;

    auto load_stage = [&](int s, int kt) {
#pragma unroll
        for (int p = 0; p < 2; p++) {
            int e = tid + p * 128, r = e >> 2, c = (e & 3) * 8;
            cp_async16(smaddr(&Kh[s][r][c]), &g_Khi[h][kt + r][c]);
            cp_async16(smaddr(&Kl[s][r][c]), &g_Klo[h][kt + r][c]);
        }
#pragma unroll
        for (int p = 0; p < 2; p++) {
            int e = tid + p * 128, r = e >> 3, c = (e & 7) * 8;
            cp_async16(smaddr(&Vh[s][r][c]), &g_Vthi[h][r][kt + c]);
            cp_async16(smaddr(&Vl[s][r][c]), &g_Vtlo[h][r][kt + c]);
        }
    };

    // Q fragments (hi/lo), 2 k-chunks of 16
    uint32_t qh[2][4], ql[2][4];
#pragma unroll
    for (int kc = 0; kc < 2; kc++) {
        qh[kc][0] = *(const uint32_t*)&g_Qhi[h][q0 + r0][kc * 16 + c0];
        qh[kc][1] = *(const uint32_t*)&g_Qhi[h][q0 + r0 + 8][kc * 16 + c0];
        qh[kc][2] = *(const uint32_t*)&g_Qhi[h][q0 + r0][kc * 16 + c0 + 8];
        qh[kc][3] = *(const uint32_t*)&g_Qhi[h][q0 + r0 + 8][kc * 16 + c0 + 8];
        ql[kc][0] = *(const uint32_t*)&g_Qlo[h][q0 + r0][kc * 16 + c0];
        ql[kc][1] = *(const uint32_t*)&g_Qlo[h][q0 + r0 + 8][kc * 16 + c0];
        ql[kc][2] = *(const uint32_t*)&g_Qlo[h][q0 + r0][kc * 16 + c0 + 8];
        ql[kc][3] = *(const uint32_t*)&g_Qlo[h][q0 + r0 + 8][kc * 16 + c0 + 8];
    }

    float o[4][4];
#pragma unroll
    for (int n = 0; n < 4; n++)
#pragma unroll
        for (int j = 0; j < 4; j++) o[n][j] = 0.0f;
    float mr[2] = { -1e30f, -1e30f };
    float lr[2] = { 0.0f, 0.0f };

    load_stage(0, z * 64); cp_commit();

    const int NIT = SLEN / 64 / NSPLIT;   // 8
    for (int it = 0; it < NIT; it++) {
        const int kt = (it * NSPLIT + z) * 64;
        const int buf = it & 1;
        cp_wait<0>();
        __syncthreads();
        if (it + 1 < NIT) { load_stage(buf ^ 1, kt + NSPLIT * 64); cp_commit(); }

        // bias prefetch into registers (consumed after QK MMAs)
        float2 bb0[8], bb1[8];
        const float* bp = &bias[(size_t)(h * SLEN + q0 + r0) * SLEN + kt + c0];
#pragma unroll
        for (int n = 0; n < 8; n++) {
            bb0[n] = *(const float2*)(bp + n * 8);
            bb1[n] = *(const float2*)(bp + 8 * SLEN + n * 8);
        }

        // S = Q K^T  (3-term split)
        float s[8][4];
#pragma unroll
        for (int n = 0; n < 8; n++) {
            s[n][0] = s[n][1] = s[n][2] = s[n][3] = 0.0f;
#pragma unroll
            for (int kc = 0; kc < 2; kc++) {
                uint32_t bh0 = *(const uint32_t*)&Kh[buf][n * 8 + r0][kc * 16 + c0];
                uint32_t bh1 = *(const uint32_t*)&Kh[buf][n * 8 + r0][kc * 16 + c0 + 8];
                uint32_t bl0 = *(const uint32_t*)&Kl[buf][n * 8 + r0][kc * 16 + c0];
                uint32_t bl1 = *(const uint32_t*)&Kl[buf][n * 8 + r0][kc * 16 + c0 + 8];
                mma_bf16(s[n], qh[kc], bh0, bh1);
                mma_bf16(s[n], qh[kc], bl0, bl1);
                mma_bf16(s[n], ql[kc], bh0, bh1);
            }
        }
        // add bias, track row max
        float mx[2] = { -1e30f, -1e30f };
#pragma unroll
        for (int n = 0; n < 8; n++) {
            s[n][0] += bb0[n].x; s[n][1] += bb0[n].y;
            s[n][2] += bb1[n].x; s[n][3] += bb1[n].y;
            mx[0] = fmaxf(mx[0], fmaxf(s[n][0], s[n][1]));
            mx[1] = fmaxf(mx[1], fmaxf(s[n][2], s[n][3]));
        }
#pragma unroll
        for (int i = 0; i < 2; i++) {
            mx[i] = fmaxf(mx[i], __shfl_xor_sync(0xffffffffu, mx[i], 1));
            mx[i] = fmaxf(mx[i], __shfl_xor_sync(0xffffffffu, mx[i], 2));
        }
        float mn[2] = { fmaxf(mr[0], mx[0]), fmaxf(mr[1], mx[1]) };
        float rs[2] = { ex2f((mr[0] - mn[0]) * LOG2E), ex2f((mr[1] - mn[1]) * LOG2E) };
        mr[0] = mn[0]; mr[1] = mn[1];
#pragma unroll
        for (int n = 0; n < 4; n++) {
            o[n][0] *= rs[0]; o[n][1] *= rs[0]; o[n][2] *= rs[1]; o[n][3] *= rs[1];
        }
        float sm[2] = { 0.0f, 0.0f };
#pragma unroll
        for (int n = 0; n < 8; n++)
#pragma unroll
            for (int j = 0; j < 4; j++) {
                float p = ex2f((s[n][j] - mn[j >> 1]) * LOG2E);
                s[n][j] = p;
                sm[j >> 1] += p;
            }
#pragma unroll
        for (int i = 0; i < 2; i++) {
            sm[i] += __shfl_xor_sync(0xffffffffu, sm[i], 1);
            sm[i] += __shfl_xor_sync(0xffffffffu, sm[i], 2);
            lr[i] = lr[i] * rs[i] + sm[i];
        }
        // pack P into split bf16 A-fragments
        uint32_t ph[4][4], pl[4][4];
#pragma unroll
        for (int kc = 0; kc < 4; kc++) {
            splitp(s[2 * kc][0],     s[2 * kc][1],     ph[kc][0], pl[kc][0]);
            splitp(s[2 * kc][2],     s[2 * kc][3],     ph[kc][1], pl[kc][1]);
            splitp(s[2 * kc + 1][0], s[2 * kc + 1][1], ph[kc][2], pl[kc][2]);
            splitp(s[2 * kc + 1][2], s[2 * kc + 1][3], ph[kc][3], pl[kc][3]);
        }
        // O += P V  (3-term split)
#pragma unroll
        for (int n = 0; n < 4; n++)
#pragma unroll
            for (int kc = 0; kc < 4; kc++) {
                uint32_t vh0 = *(const uint32_t*)&Vh[buf][n * 8 + r0][kc * 16 + c0];
                uint32_t vh1 = *(const uint32_t*)&Vh[buf][n * 8 + r0][kc * 16 + c0 + 8];
                uint32_t vl0 = *(const uint32_t*)&Vl[buf][n * 8 + r0][kc * 16 + c0];
                uint32_t vl1 = *(const uint32_t*)&Vl[buf][n * 8 + r0][kc * 16 + c0 + 8];
                mma_bf16(o[n], ph[kc], vh0, vh1);
                mma_bf16(o[n], ph[kc], vl0, vl1);
                mma_bf16(o[n], pl[kc], vh0, vh1);
            }
    }
    // epilogue: write unnormalized partials (O, m, l)
#pragma unroll
    for (int n = 0; n < 4; n++) {
        float2 w0 = { o[n][0], o[n][1] };
        float2 w1 = { o[n][2], o[n][3] };
        *(float2*)&g_Opart[z][h][q0 + r0][n * 8 + c0] = w0;
        *(float2*)&g_Opart[z][h][q0 + r0 + 8][n * 8 + c0] = w1;
    }
    if ((ln & 3) == 0) {
        g_ml[z][h][q0 + r0][0] = mr[0];
        g_ml[z][h][q0 + r0][1] = lr[0];
        g_ml[z][h][q0 + r0 + 8][0] = mr[1];
        g_ml[z][h][q0 + r0 + 8][1] = lr[1];
    }
}

// =============== kernel 2b: split-K merge + gate ===============
__global__ __launch_bounds__(256) void merge_kernel()
{
    int t = blockIdx.x * 256 + threadIdx.x;   // one (h, q) row per thread
    int h = t >> 11, q = t & 2047;
    float m = -1e30f;
    float mv[NSPLIT], lv[NSPLIT];
#pragma unroll
    for (int p = 0; p < NSPLIT; p++) {
        mv[p] = g_ml[p][h][q][0];
        lv[p] = g_ml[p][h][q][1];
        m = fmaxf(m, mv[p]);
    }
    float a[NSPLIT], lsum = 0.0f;
#pragma unroll
    for (int p = 0; p < NSPLIT; p++) {
        a[p] = ex2f((mv[p] - m) * LOG2E);
        lsum += lv[p] * a[p];
    }
    float rl = 1.0f / lsum;
#pragma unroll
    for (int p = 0; p < NSPLIT; p++) a[p] *= rl;
#pragma unroll
    for (int c = 0; c < 32; c += 4) {
        float4 r = { 0.0f, 0.0f, 0.0f, 0.0f };
#pragma unroll
        for (int p = 0; p < NSPLIT; p++) {
            float4 x = *(const float4*)&g_Opart[p][h][q][c];
            r.x += x.x * a[p]; r.y += x.y * a[p];
            r.z += x.z * a[p]; r.w += x.w * a[p];
        }
        float4 gg = *(const float4*)&g_G[h][q][c];
        r.x *= gg.x; r.y *= gg.y; r.z *= gg.z; r.w *= gg.w;
        *(float4*)&g_AO[q][h * 32 + c] = r;
    }
}

// =============== kernel 3: output projection (fp32 f32x2, 256 thr, 4x4/thread) ===============
__global__ __launch_bounds__(256) void outproj_kernel(
    float* __restrict__ out, const float* __restrict__ W, const float* __restrict__ Bv)
{
    __shared__ __align__(16) float As[2][64][20];
    __shared__ __align__(16) float Bs[2][16][64];
    const int m0 = blockIdx.y * 64, n0b = blockIdx.x * 64;
    const int tid = threadIdx.x, tx = tid & 15, ty = tid >> 4;

    unsigned long long acc[4][2];
#pragma unroll
    for (int i = 0; i < 4; i++) { acc[i][0] = 0ull; acc[i][1] = 0ull; }

    auto load_stage = [&](int s, int kt) {
        {
            int r = tid >> 2, kq = tid & 3;
            cp_async16(smaddr(&As[s][r][kq * 4]), &g_AO[m0 + r][kt + kq * 4]);
        }
        {
            int k = tid >> 4, nq = tid & 15;
            cp_async16(smaddr(&Bs[s][k][nq * 4]), &W[(kt + k) * 256 + n0b + nq * 4]);
        }
    };

    load_stage(0, 0); cp_commit();

    for (int it = 0; it < 16; it++) {
        const int buf = it & 1;
        cp_wait<0>();
        __syncthreads();
        if (it + 1 < 16) { load_stage(buf ^ 1, (it + 1) * 16); cp_commit(); }
#pragma unroll
        for (int k = 0; k < 16; k++) {
            unsigned long long b0 = pk2(*(const float2*)&Bs[buf][k][tx * 4]);
            unsigned long long b1 = pk2(*(const float2*)&Bs[buf][k][tx * 4 + 2]);
#pragma unroll
            for (int i = 0; i < 4; i++) {
                unsigned long long a = dup2(As[buf][ty * 4 + i][k]);
                fma2(acc[i][0], a, b0);
                fma2(acc[i][1], a, b1);
            }
        }
        __syncthreads();
    }
#pragma unroll
    for (int i = 0; i < 4; i++) {
        int q = m0 + ty * 4 + i;
#pragma unroll
        for (int j = 0; j < 2; j++) {
            int col = n0b + tx * 4 + j * 2;
            float2 v = unpack2(acc[i][j]);
            v.x += Bv[col]; v.y += Bv[col + 1];
            *(float2*)&out[q * 256 + col] = v;
        }
    }
}

// =============== launch ===============
extern "C" void kernel_launch(void* const* d_in, const int* in_sizes, int n_in,
                              void* d_out, int out_size) {
    const float* q_inputs   = (const float*)d_in[0];
    const float* kv_inputs  = (const float*)d_in[1];
    const float* bias       = (const float*)d_in[2];
    const float* qg_weights = (const float*)d_in[3];
    const float* kv_weights = (const float*)d_in[4];
    const float* qg_bias    = (const float*)d_in[5];
    const float* kv_bias    = (const float*)d_in[6];
    const float* o_weights  = (const float*)d_in[7];
    const float* o_bias     = (const float*)d_in[8];
    float* out = (float*)d_out;

    proj_kernel<<<dim3(8, 32, 2), 128>>>(q_inputs, kv_inputs, qg_weights, kv_weights,
                                         qg_bias, kv_bias);
    attn_kernel<<<dim3(32, 8, NSPLIT), 128>>>(bias);
    merge_kernel<<<64, 256>>>();
    outproj_kernel<<<dim3(4, 32), 256>>>(out, o_weights, o_bias);
}

// round 8
// speedup vs baseline: 1.6152x; 1.6152x over previous
#include <cuda_runtime.h>
#include <cuda_bf16.h>
#include <stdint.h>

#define NHEAD 8
#define SLEN 2048
#define NSPLIT 2
#define SCALE 0.17677669529663689f
#define LOG2E 1.4426950408889634f

// ------------- device scratch (no allocation allowed) -------------
static __device__ __align__(16) __nv_bfloat16 g_Qhi[NHEAD][SLEN][32], g_Qlo[NHEAD][SLEN][32];
static __device__ __align__(16) __nv_bfloat16 g_Khi[NHEAD][SLEN][32], g_Klo[NHEAD][SLEN][32];
static __device__ __align__(16) __nv_bfloat16 g_Vthi[NHEAD][32][SLEN], g_Vtlo[NHEAD][32][SLEN];
static __device__ __align__(16) float g_G[NHEAD][SLEN][32];
static __device__ __align__(16) float g_AO[SLEN][256];
static __device__ __align__(16) float g_Opart[NSPLIT][NHEAD][SLEN][32];
static __device__ __align__(16) float g_ml[NSPLIT][NHEAD][SLEN][2];

// ------------- helpers -------------
__device__ __forceinline__ unsigned long long dup2(float x) {
    unsigned long long r; asm("mov.b64 %0, {%1,%1};" : "=l"(r) : "f"(x)); return r;
}
__device__ __forceinline__ unsigned long long pk2(float2 v) {
    unsigned long long r; asm("mov.b64 %0, {%1,%2};" : "=l"(r) : "f"(v.x), "f"(v.y)); return r;
}
__device__ __forceinline__ void fma2(unsigned long long &d, unsigned long long a, unsigned long long b) {
    asm("fma.rn.f32x2 %0, %1, %2, %0;" : "+l"(d) : "l"(a), "l"(b));
}
__device__ __forceinline__ float2 unpack2(unsigned long long v) {
    float2 r; asm("mov.b64 {%0,%1}, %2;" : "=f"(r.x), "=f"(r.y) : "l"(v)); return r;
}
__device__ __forceinline__ float ex2f(float x) {
    float y; asm("ex2.approx.f32 %0, %1;" : "=f"(y) : "f"(x)); return y;
}
__device__ __forceinline__ uint32_t packbf(float lo, float hi) {
    uint32_t r; asm("cvt.rn.bf16x2.f32 %0, %1, %2;" : "=r"(r) : "f"(hi), "f"(lo)); return r;
}
__device__ __forceinline__ void splitp(float x, float y, uint32_t &hi, uint32_t &lo) {
    hi = packbf(x, y);
    float xh = __uint_as_float(hi << 16);
    float yh = __uint_as_float(hi & 0xffff0000u);
    lo = packbf(x - xh, y - yh);
}
__device__ __forceinline__ void mma_bf16(float* d, const uint32_t* a, uint32_t b0, uint32_t b1) {
    asm volatile("mma.sync.aligned.m16n8k16.row.col.f32.bf16.bf16.f32 "
        "{%0,%1,%2,%3},{%4,%5,%6,%7},{%8,%9},{%0,%1,%2,%3};"
        : "+f"(d[0]), "+f"(d[1]), "+f"(d[2]), "+f"(d[3])
        : "r"(a[0]), "r"(a[1]), "r"(a[2]), "r"(a[3]), "r"(b0), "r"(b1));
}
__device__ __forceinline__ uint32_t smaddr(const void* p) {
    return (uint32_t)__cvta_generic_to_shared(p);
}
__device__ __forceinline__ void cp_async16(uint32_t s, const void* g) {
    asm volatile("cp.async.cg.shared.global [%0], [%1], 16;" :: "r"(s), "l"(g));
}
__device__ __forceinline__ void cp_commit() { asm volatile("cp.async.commit_group;"); }
template<int N> __device__ __forceinline__ void cp_wait() {
    asm volatile("cp.async.wait_group %0;" :: "n"(N));
}

// =============== kernel 1: input projections (fp32 f32x2, double-buffered) ===============
__global__ __launch_bounds__(128) void proj_kernel(
    const float* __restrict__ Xq, const float* __restrict__ Xkv,
    const float* __restrict__ Wq, const float* __restrict__ Wk,
    const float* __restrict__ Bq, const float* __restrict__ Bk)
{
    __shared__ __align__(16) float As[2][64][20];
    __shared__ __align__(16) float Bs[2][16][64];
    const int z = blockIdx.z;
    const float* __restrict__ X  = z ? Xkv : Xq;
    const float* __restrict__ W  = z ? Wk  : Wq;
    const float* __restrict__ Bv = z ? Bk  : Bq;
    const int m0 = blockIdx.y * 64, n0b = blockIdx.x * 64;
    const int tid = threadIdx.x, tx = tid & 15, ty = tid >> 4;

    unsigned long long acc[8][2];
#pragma unroll
    for (int i = 0; i < 8; i++) { acc[i][0] = 0ull; acc[i][1] = 0ull; }

    auto load_stage = [&](int s, int kt) {
#pragma unroll
        for (int p = 0; p < 2; p++) {
            int e = tid + p * 128, r = e >> 2, kq = e & 3;
            cp_async16(smaddr(&As[s][r][kq * 4]), &X[(m0 + r) * 256 + kt + kq * 4]);
        }
#pragma unroll
        for (int p = 0; p < 2; p++) {
            int e = tid + p * 128, k = e >> 4, nq = e & 15;
            cp_async16(smaddr(&Bs[s][k][nq * 4]), &W[(kt + k) * 512 + n0b + nq * 4]);
        }
    };

    load_stage(0, 0); cp_commit();

    for (int it = 0; it < 16; it++) {
        const int buf = it & 1;
        cp_wait<0>();
        __syncthreads();
        if (it + 1 < 16) { load_stage(buf ^ 1, (it + 1) * 16); cp_commit(); }
#pragma unroll
        for (int k = 0; k < 16; k++) {
            unsigned long long b0 = pk2(*(const float2*)&Bs[buf][k][tx * 4]);
            unsigned long long b1 = pk2(*(const float2*)&Bs[buf][k][tx * 4 + 2]);
#pragma unroll
            for (int i = 0; i < 8; i++) {
                unsigned long long a = dup2(As[buf][ty * 8 + i][k]);
                fma2(acc[i][0], a, b0);
                fma2(acc[i][1], a, b1);
            }
        }
        __syncthreads();
    }
#pragma unroll
    for (int i = 0; i < 8; i++) {
        int q = m0 + ty * 8 + i;
#pragma unroll
        for (int j = 0; j < 2; j++) {
            float2 v = unpack2(acc[i][j]);
            float vv[2] = { v.x, v.y };
#pragma unroll
            for (int e = 0; e < 2; e++) {
                int col = n0b + tx * 4 + j * 2 + e;
                int h = col >> 6, cc = col & 63;
                float x = vv[e] + Bv[col];
                if (z == 0) {
                    if (cc < 32) {
                        float s = x * SCALE;
                        __nv_bfloat16 hi = __float2bfloat16(s);
                        g_Qhi[h][q][cc] = hi;
                        g_Qlo[h][q][cc] = __float2bfloat16(s - __bfloat162float(hi));
                    } else {
                        g_G[h][q][cc - 32] = 1.0f / (1.0f + __expf(-x));
                    }
                } else {
                    __nv_bfloat16 hi = __float2bfloat16(x);
                    float lo = x - __bfloat162float(hi);
                    if (cc < 32) {
                        g_Khi[h][q][cc] = hi; g_Klo[h][q][cc] = __float2bfloat16(lo);
                    } else {
                        g_Vthi[h][cc - 32][q] = hi; g_Vtlo[h][cc - 32][q] = __float2bfloat16(lo);
                    }
                }
            }
        }
    }
}

// =============== kernel 2: flash attention, split-K x2, bias cp.async pipeline ===============
// dynamic smem layout (bytes):
//   Kh: 64x40 bf16            @ 0       (5120)
//   Kl: 64x40 bf16            @ 5120    (5120)
//   Vh: 32x72 bf16            @ 10240   (4608)
//   Vl: 32x72 bf16            @ 14848   (4608)
//   Bias: 2 stages x 64x68 f32 @ 19456  (34816)   total = 54272
#define ATTN_SMEM 54272
__global__ __launch_bounds__(128, 4) void attn_kernel(const float* __restrict__ bias)
{
    extern __shared__ __align__(16) char dynsm[];
    __nv_bfloat16 (*Kh)[40] = (__nv_bfloat16(*)[40])(dynsm);
    __nv_bfloat16 (*Kl)[40] = (__nv_bfloat16(*)[40])(dynsm + 5120);
    __nv_bfloat16 (*Vh)[72] = (__nv_bfloat16(*)[72])(dynsm + 10240);
    __nv_bfloat16 (*Vl)[72] = (__nv_bfloat16(*)[72])(dynsm + 14848);
    float* biasS = (float*)(dynsm + 19456);
#define BIASS(s, r, c) biasS[((s) * 64 + (r)) * 68 + (c)]

    const int h = blockIdx.y;
    const int z = blockIdx.z;
    const int tid = threadIdx.x, wid = tid >> 5, ln = tid & 31;
    const int q0b = blockIdx.x * 64;
    const int q0 = q0b + wid * 16;
    const int r0 = ln >> 2, c0 = (ln & 3) * 2;

    auto load_kv = [&](int kt) {
#pragma unroll
        for (int p = 0; p < 2; p++) {
            int e = tid + p * 128, r = e >> 2, c = (e & 3) * 8;
            cp_async16(smaddr(&Kh[r][c]), &g_Khi[h][kt + r][c]);
            cp_async16(smaddr(&Kl[r][c]), &g_Klo[h][kt + r][c]);
        }
#pragma unroll
        for (int p = 0; p < 2; p++) {
            int e = tid + p * 128, r = e >> 3, c = (e & 7) * 8;
            cp_async16(smaddr(&Vh[r][c]), &g_Vthi[h][r][kt + c]);
            cp_async16(smaddr(&Vl[r][c]), &g_Vtlo[h][r][kt + c]);
        }
    };
    auto load_bias = [&](int s, int kt) {
#pragma unroll
        for (int p = 0; p < 8; p++) {
            int e = tid + p * 128, r = e >> 4, seg = e & 15;
            cp_async16(smaddr(&BIASS(s, r, seg * 4)),
                       &bias[(size_t)(h * SLEN + q0b + r) * SLEN + kt + seg * 4]);
        }
    };

    // Q fragments (hi/lo), 2 k-chunks of 16
    uint32_t qh[2][4], ql[2][4];
#pragma unroll
    for (int kc = 0; kc < 2; kc++) {
        qh[kc][0] = *(const uint32_t*)&g_Qhi[h][q0 + r0][kc * 16 + c0];
        qh[kc][1] = *(const uint32_t*)&g_Qhi[h][q0 + r0 + 8][kc * 16 + c0];
        qh[kc][2] = *(const uint32_t*)&g_Qhi[h][q0 + r0][kc * 16 + c0 + 8];
        qh[kc][3] = *(const uint32_t*)&g_Qhi[h][q0 + r0 + 8][kc * 16 + c0 + 8];
        ql[kc][0] = *(const uint32_t*)&g_Qlo[h][q0 + r0][kc * 16 + c0];
        ql[kc][1] = *(const uint32_t*)&g_Qlo[h][q0 + r0 + 8][kc * 16 + c0];
        ql[kc][2] = *(const uint32_t*)&g_Qlo[h][q0 + r0][kc * 16 + c0 + 8];
        ql[kc][3] = *(const uint32_t*)&g_Qlo[h][q0 + r0 + 8][kc * 16 + c0 + 8];
    }

    float o[4][4];
#pragma unroll
    for (int n = 0; n < 4; n++)
#pragma unroll
        for (int j = 0; j < 4; j++) o[n][j] = 0.0f;
    float mr[2] = { -1e30f, -1e30f };
    float lr[2] = { 0.0f, 0.0f };

    // prologue: bias tile 0 in flight
    load_bias(0, z * 64); cp_commit();

    const int NIT = SLEN / 64 / NSPLIT;   // 16
    for (int it = 0; it < NIT; it++) {
        const int kt = (it * NSPLIT + z) * 64;
        const int bbuf = it & 1;
        __syncthreads();   // previous iteration's smem reads complete
        load_kv(kt); cp_commit();                                   // group A_i
        if (it + 1 < NIT) { load_bias(bbuf ^ 1, kt + NSPLIT * 64); cp_commit(); } // group B_i
        if (it + 1 < NIT) cp_wait<1>(); else cp_wait<0>();
        __syncthreads();

        // S = Q K^T  (3-term split)
        float s[8][4];
#pragma unroll
        for (int n = 0; n < 8; n++) {
            s[n][0] = s[n][1] = s[n][2] = s[n][3] = 0.0f;
#pragma unroll
            for (int kc = 0; kc < 2; kc++) {
                uint32_t bh0 = *(const uint32_t*)&Kh[n * 8 + r0][kc * 16 + c0];
                uint32_t bh1 = *(const uint32_t*)&Kh[n * 8 + r0][kc * 16 + c0 + 8];
                uint32_t bl0 = *(const uint32_t*)&Kl[n * 8 + r0][kc * 16 + c0];
                uint32_t bl1 = *(const uint32_t*)&Kl[n * 8 + r0][kc * 16 + c0 + 8];
                mma_bf16(s[n], qh[kc], bh0, bh1);
                mma_bf16(s[n], qh[kc], bl0, bl1);
                mma_bf16(s[n], ql[kc], bh0, bh1);
            }
        }
        // add bias (from smem pipeline), track row max
        float mx[2] = { -1e30f, -1e30f };
        const int br0 = wid * 16 + r0;
#pragma unroll
        for (int n = 0; n < 8; n++) {
            float2 b0 = *(const float2*)&BIASS(bbuf, br0, n * 8 + c0);
            float2 b1 = *(const float2*)&BIASS(bbuf, br0 + 8, n * 8 + c0);
            s[n][0] += b0.x; s[n][1] += b0.y;
            s[n][2] += b1.x; s[n][3] += b1.y;
            mx[0] = fmaxf(mx[0], fmaxf(s[n][0], s[n][1]));
            mx[1] = fmaxf(mx[1], fmaxf(s[n][2], s[n][3]));
        }
#pragma unroll
        for (int i = 0; i < 2; i++) {
            mx[i] = fmaxf(mx[i], __shfl_xor_sync(0xffffffffu, mx[i], 1));
            mx[i] = fmaxf(mx[i], __shfl_xor_sync(0xffffffffu, mx[i], 2));
        }
        float mn[2] = { fmaxf(mr[0], mx[0]), fmaxf(mr[1], mx[1]) };
        float rs[2] = { ex2f((mr[0] - mn[0]) * LOG2E), ex2f((mr[1] - mn[1]) * LOG2E) };
        mr[0] = mn[0]; mr[1] = mn[1];
#pragma unroll
        for (int n = 0; n < 4; n++) {
            o[n][0] *= rs[0]; o[n][1] *= rs[0]; o[n][2] *= rs[1]; o[n][3] *= rs[1];
        }
        float sm[2] = { 0.0f, 0.0f };
#pragma unroll
        for (int n = 0; n < 8; n++)
#pragma unroll
            for (int j = 0; j < 4; j++) {
                float p = ex2f((s[n][j] - mn[j >> 1]) * LOG2E);
                s[n][j] = p;
                sm[j >> 1] += p;
            }
#pragma unroll
        for (int i = 0; i < 2; i++) {
            sm[i] += __shfl_xor_sync(0xffffffffu, sm[i], 1);
            sm[i] += __shfl_xor_sync(0xffffffffu, sm[i], 2);
            lr[i] = lr[i] * rs[i] + sm[i];
        }
        // pack P into split bf16 A-fragments
        uint32_t ph[4][4], pl[4][4];
#pragma unroll
        for (int kc = 0; kc < 4; kc++) {
            splitp(s[2 * kc][0],     s[2 * kc][1],     ph[kc][0], pl[kc][0]);
            splitp(s[2 * kc][2],     s[2 * kc][3],     ph[kc][1], pl[kc][1]);
            splitp(s[2 * kc + 1][0], s[2 * kc + 1][1], ph[kc][2], pl[kc][2]);
            splitp(s[2 * kc + 1][2], s[2 * kc + 1][3], ph[kc][3], pl[kc][3]);
        }
        // O += P V  (3-term split)
#pragma unroll
        for (int n = 0; n < 4; n++)
#pragma unroll
            for (int kc = 0; kc < 4; kc++) {
                uint32_t vh0 = *(const uint32_t*)&Vh[n * 8 + r0][kc * 16 + c0];
                uint32_t vh1 = *(const uint32_t*)&Vh[n * 8 + r0][kc * 16 + c0 + 8];
                uint32_t vl0 = *(const uint32_t*)&Vl[n * 8 + r0][kc * 16 + c0];
                uint32_t vl1 = *(const uint32_t*)&Vl[n * 8 + r0][kc * 16 + c0 + 8];
                mma_bf16(o[n], ph[kc], vh0, vh1);
                mma_bf16(o[n], ph[kc], vl0, vl1);
                mma_bf16(o[n], pl[kc], vh0, vh1);
            }
    }
    // epilogue: write unnormalized partials (O, m, l)
#pragma unroll
    for (int n = 0; n < 4; n++) {
        float2 w0 = { o[n][0], o[n][1] };
        float2 w1 = { o[n][2], o[n][3] };
        *(float2*)&g_Opart[z][h][q0 + r0][n * 8 + c0] = w0;
        *(float2*)&g_Opart[z][h][q0 + r0 + 8][n * 8 + c0] = w1;
    }
    if ((ln & 3) == 0) {
        g_ml[z][h][q0 + r0][0] = mr[0];
        g_ml[z][h][q0 + r0][1] = lr[0];
        g_ml[z][h][q0 + r0 + 8][0] = mr[1];
        g_ml[z][h][q0 + r0 + 8][1] = lr[1];
    }
#undef BIASS
}

// =============== kernel 2b: split-K merge + gate ===============
__global__ __launch_bounds__(256) void merge_kernel()
{
    int t = blockIdx.x * 256 + threadIdx.x;   // one (h, q) row per thread
    int h = t >> 11, q = t & 2047;
    float m = -1e30f;
    float mv[NSPLIT], lv[NSPLIT];
#pragma unroll
    for (int p = 0; p < NSPLIT; p++) {
        mv[p] = g_ml[p][h][q][0];
        lv[p] = g_ml[p][h][q][1];
        m = fmaxf(m, mv[p]);
    }
    float a[NSPLIT], lsum = 0.0f;
#pragma unroll
    for (int p = 0; p < NSPLIT; p++) {
        a[p] = ex2f((mv[p] - m) * LOG2E);
        lsum += lv[p] * a[p];
    }
    float rl = 1.0f / lsum;
#pragma unroll
    for (int p = 0; p < NSPLIT; p++) a[p] *= rl;
#pragma unroll
    for (int c = 0; c < 32; c += 4) {
        float4 r = { 0.0f, 0.0f, 0.0f, 0.0f };
#pragma unroll
        for (int p = 0; p < NSPLIT; p++) {
            float4 x = *(const float4*)&g_Opart[p][h][q][c];
            r.x += x.x * a[p]; r.y += x.y * a[p];
            r.z += x.z * a[p]; r.w += x.w * a[p];
        }
        float4 gg = *(const float4*)&g_G[h][q][c];
        r.x *= gg.x; r.y *= gg.y; r.z *= gg.z; r.w *= gg.w;
        *(float4*)&g_AO[q][h * 32 + c] = r;
    }
}

// =============== kernel 3: output projection (fp32 f32x2, 128 thr, 8 rows/thread) ===============
__global__ __launch_bounds__(128) void outproj_kernel(
    float* __restrict__ out, const float* __restrict__ W, const float* __restrict__ Bv)
{
    __shared__ __align__(16) float As[2][64][20];
    __shared__ __align__(16) float Bs[2][16][64];
    const int m0 = blockIdx.y * 64, n0b = blockIdx.x * 64;
    const int tid = threadIdx.x, tx = tid & 15, ty = tid >> 4;

    unsigned long long acc[8][2];
#pragma unroll
    for (int i = 0; i < 8; i++) { acc[i][0] = 0ull; acc[i][1] = 0ull; }

    auto load_stage = [&](int s, int kt) {
#pragma unroll
        for (int p = 0; p < 2; p++) {
            int e = tid + p * 128, r = e >> 2, kq = e & 3;
            cp_async16(smaddr(&As[s][r][kq * 4]), &g_AO[m0 + r][kt + kq * 4]);
        }
#pragma unroll
        for (int p = 0; p < 2; p++) {
            int e = tid + p * 128, k = e >> 4, nq = e & 15;
            cp_async16(smaddr(&Bs[s][k][nq * 4]), &W[(kt + k) * 256 + n0b + nq * 4]);
        }
    };

    load_stage(0, 0); cp_commit();

    for (int it = 0; it < 16; it++) {
        const int buf = it & 1;
        cp_wait<0>();
        __syncthreads();
        if (it + 1 < 16) { load_stage(buf ^ 1, (it + 1) * 16); cp_commit(); }
#pragma unroll
        for (int k = 0; k < 16; k++) {
            unsigned long long b0 = pk2(*(const float2*)&Bs[buf][k][tx * 4]);
            unsigned long long b1 = pk2(*(const float2*)&Bs[buf][k][tx * 4 + 2]);
#pragma unroll
            for (int i = 0; i < 8; i++) {
                unsigned long long a = dup2(As[buf][ty * 8 + i][k]);
                fma2(acc[i][0], a, b0);
                fma2(acc[i][1], a, b1);
            }
        }
        __syncthreads();
    }
#pragma unroll
    for (int i = 0; i < 8; i++) {
        int q = m0 + ty * 8 + i;
#pragma unroll
        for (int j = 0; j < 2; j++) {
            int col = n0b + tx * 4 + j * 2;
            float2 v = unpack2(acc[i][j]);
            v.x += Bv[col]; v.y += Bv[col + 1];
            *(float2*)&out[q * 256 + col] = v;
        }
    }
}

// =============== launch ===============
extern "C" void kernel_launch(void* const* d_in, const int* in_sizes, int n_in,
                              void* d_out, int out_size) {
    const float* q_inputs   = (const float*)d_in[0];
    const float* kv_inputs  = (const float*)d_in[1];
    const float* bias       = (const float*)d_in[2];
    const float* qg_weights = (const float*)d_in[3];
    const float* kv_weights = (const float*)d_in[4];
    const float* qg_bias    = (const float*)d_in[5];
    const float* kv_bias    = (const float*)d_in[6];
    const float* o_weights  = (const float*)d_in[7];
    const float* o_bias     = (const float*)d_in[8];
    float* out = (float*)d_out;

    cudaFuncSetAttribute(attn_kernel, cudaFuncAttributeMaxDynamicSharedMemorySize, ATTN_SMEM);

    proj_kernel<<<dim3(8, 32, 2), 128>>>(q_inputs, kv_inputs, qg_weights, kv_weights,
                                         qg_bias, kv_bias);
    attn_kernel<<<dim3(32, 8, NSPLIT), 128, ATTN_SMEM>>>(bias);
    merge_kernel<<<64, 256>>>();
    outproj_kernel<<<dim3(4, 32), 128>>>(out, o_weights, o_bias);
}

// round 9
// speedup vs baseline: 1.7664x; 1.0936x over previous
#include <cuda_runtime.h>
#include <cuda_bf16.h>
#include <stdint.h>

#define NHEAD 8
#define SLEN 2048
#define NSPLIT 2
#define SCALE 0.17677669529663689f
#define LOG2E 1.4426950408889634f

// ------------- device scratch (no allocation allowed) -------------
static __device__ __align__(16) __nv_bfloat16 g_Qhi[NHEAD][SLEN][32], g_Qlo[NHEAD][SLEN][32];
static __device__ __align__(16) __nv_bfloat16 g_Khi[NHEAD][SLEN][32], g_Klo[NHEAD][SLEN][32];
static __device__ __align__(16) __nv_bfloat16 g_Vthi[NHEAD][32][SLEN], g_Vtlo[NHEAD][32][SLEN];
static __device__ __align__(16) float g_G[NHEAD][SLEN][32];
static __device__ __align__(16) float g_Opart[NSPLIT][NHEAD][SLEN][32];
static __device__ __align__(16) float g_ml[NSPLIT][NHEAD][SLEN][2];
// split-bf16 inputs for MMA projections
static __device__ __align__(16) __nv_bfloat16 g_Xqhi[SLEN * 256], g_Xqlo[SLEN * 256];
static __device__ __align__(16) __nv_bfloat16 g_Xkhi[SLEN * 256], g_Xklo[SLEN * 256];
static __device__ __align__(16) __nv_bfloat16 g_Wqthi[512 * 256], g_Wqtlo[512 * 256];
static __device__ __align__(16) __nv_bfloat16 g_Wkthi[512 * 256], g_Wktlo[512 * 256];
static __device__ __align__(16) __nv_bfloat16 g_Wothi[256 * 256], g_Wotlo[256 * 256];
static __device__ __align__(16) __nv_bfloat16 g_AOhi[SLEN * 256], g_AOlo[SLEN * 256];

// ------------- helpers -------------
__device__ __forceinline__ float ex2f(float x) {
    float y; asm("ex2.approx.f32 %0, %1;" : "=f"(y) : "f"(x)); return y;
}
__device__ __forceinline__ uint32_t packbf(float lo, float hi) {
    uint32_t r; asm("cvt.rn.bf16x2.f32 %0, %1, %2;" : "=r"(r) : "f"(hi), "f"(lo)); return r;
}
__device__ __forceinline__ void splitp(float x, float y, uint32_t &hi, uint32_t &lo) {
    hi = packbf(x, y);
    float xh = __uint_as_float(hi << 16);
    float yh = __uint_as_float(hi & 0xffff0000u);
    lo = packbf(x - xh, y - yh);
}
__device__ __forceinline__ void mma_bf16(float* d, const uint32_t* a, uint32_t b0, uint32_t b1) {
    asm volatile("mma.sync.aligned.m16n8k16.row.col.f32.bf16.bf16.f32 "
        "{%0,%1,%2,%3},{%4,%5,%6,%7},{%8,%9},{%0,%1,%2,%3};"
        : "+f"(d[0]), "+f"(d[1]), "+f"(d[2]), "+f"(d[3])
        : "r"(a[0]), "r"(a[1]), "r"(a[2]), "r"(a[3]), "r"(b0), "r"(b1));
}
__device__ __forceinline__ uint32_t smaddr(const void* p) {
    return (uint32_t)__cvta_generic_to_shared(p);
}
__device__ __forceinline__ void cp_async16(uint32_t s, const void* g) {
    asm volatile("cp.async.cg.shared.global [%0], [%1], 16;" :: "r"(s), "l"(g));
}
__device__ __forceinline__ void cp_commit() { asm volatile("cp.async.commit_group;"); }
template<int N> __device__ __forceinline__ void cp_wait() {
    asm volatile("cp.async.wait_group %0;" :: "n"(N));
}
__device__ __forceinline__ void split_store(float v, __nv_bfloat16* hi, __nv_bfloat16* lo) {
    __nv_bfloat16 h = __float2bfloat16(v);
    *hi = h;
    *lo = __float2bfloat16(v - __bfloat162float(h));
}

// =============== kernel 0: split/transposed-split prepass ===============
// regions: Xq, Xkv (copy-split), Wq^T, Wk^T, Wo^T (transpose-split)
__global__ __launch_bounds__(256) void split_kernel(
    const float* __restrict__ Xq, const float* __restrict__ Xkv,
    const float* __restrict__ Wq, const float* __restrict__ Wk,
    const float* __restrict__ Wo)
{
    const int NX = SLEN * 256;     // 524288
    const int NW = 256 * 512;      // 131072
    const int NO = 256 * 256;      // 65536
    int i = blockIdx.x * 256 + threadIdx.x;
    if (i < NX) {
        split_store(Xq[i], &g_Xqhi[i], &g_Xqlo[i]);
    } else if (i < 2 * NX) {
        int j = i - NX;
        split_store(Xkv[j], &g_Xkhi[j], &g_Xklo[j]);
    } else if (i < 2 * NX + NW) {
        int j = i - 2 * NX;                 // j = n*256 + k
        int n = j >> 8, k = j & 255;
        split_store(Wq[k * 512 + n], &g_Wqthi[j], &g_Wqtlo[j]);
    } else if (i < 2 * NX + 2 * NW) {
        int j = i - 2 * NX - NW;
        int n = j >> 8, k = j & 255;
        split_store(Wk[k * 512 + n], &g_Wkthi[j], &g_Wktlo[j]);
    } else {
        int j = i - 2 * NX - 2 * NW;
        if (j < NO) {
            int n = j >> 8, k = j & 255;
            split_store(Wo[k * 256 + n], &g_Wothi[j], &g_Wotlo[j]);
        }
    }
}

// =============== kernel 1: input projections (split-bf16 MMA) ===============
// z=0: Xq @ Wq + Bq -> Q (bf16 split, pre-scaled), sigmoid(G)
// z=1: Xkv @ Wk + Bk -> K (split), V (split, transposed)
__global__ __launch_bounds__(128) void proj_mma(
    const float* __restrict__ Bq, const float* __restrict__ Bk)
{
    __shared__ __align__(16) __nv_bfloat16 Ah[2][64][40], Al[2][64][40];
    __shared__ __align__(16) __nv_bfloat16 Bh[2][64][40], Bl[2][64][40];
    const int z = blockIdx.z;
    const __nv_bfloat16* __restrict__ Xhi  = z ? g_Xkhi  : g_Xqhi;
    const __nv_bfloat16* __restrict__ Xlo  = z ? g_Xklo  : g_Xqlo;
    const __nv_bfloat16* __restrict__ Wthi = z ? g_Wkthi : g_Wqthi;
    const __nv_bfloat16* __restrict__ Wtlo = z ? g_Wktlo : g_Wqtlo;
    const float* __restrict__ Bv = z ? Bk : Bq;
    const int m0 = blockIdx.y * 64, n0 = blockIdx.x * 64;
    const int tid = threadIdx.x, wid = tid >> 5, ln = tid & 31;
    const int r0 = ln >> 2, c0 = (ln & 3) * 2;

    auto load_stage = [&](int s, int kt) {
#pragma unroll
        for (int p = 0; p < 2; p++) {
            int e = tid + p * 128, r = e >> 2, c = (e & 3) * 8;
            cp_async16(smaddr(&Ah[s][r][c]), &Xhi[(m0 + r) * 256 + kt + c]);
            cp_async16(smaddr(&Al[s][r][c]), &Xlo[(m0 + r) * 256 + kt + c]);
            cp_async16(smaddr(&Bh[s][r][c]), &Wthi[(n0 + r) * 256 + kt + c]);
            cp_async16(smaddr(&Bl[s][r][c]), &Wtlo[(n0 + r) * 256 + kt + c]);
        }
    };

    float s[8][4];
#pragma unroll
    for (int n = 0; n < 8; n++)
#pragma unroll
        for (int j = 0; j < 4; j++) s[n][j] = 0.0f;

    load_stage(0, 0); cp_commit();

    for (int it = 0; it < 8; it++) {
        const int buf = it & 1;
        cp_wait<0>();
        __syncthreads();
        if (it + 1 < 8) { load_stage(buf ^ 1, (it + 1) * 32); cp_commit(); }

#pragma unroll
        for (int kc = 0; kc < 2; kc++) {
            uint32_t ah[4], al[4];
            ah[0] = *(const uint32_t*)&Ah[buf][wid * 16 + r0][kc * 16 + c0];
            ah[1] = *(const uint32_t*)&Ah[buf][wid * 16 + r0 + 8][kc * 16 + c0];
            ah[2] = *(const uint32_t*)&Ah[buf][wid * 16 + r0][kc * 16 + c0 + 8];
            ah[3] = *(const uint32_t*)&Ah[buf][wid * 16 + r0 + 8][kc * 16 + c0 + 8];
            al[0] = *(const uint32_t*)&Al[buf][wid * 16 + r0][kc * 16 + c0];
            al[1] = *(const uint32_t*)&Al[buf][wid * 16 + r0 + 8][kc * 16 + c0];
            al[2] = *(const uint32_t*)&Al[buf][wid * 16 + r0][kc * 16 + c0 + 8];
            al[3] = *(const uint32_t*)&Al[buf][wid * 16 + r0 + 8][kc * 16 + c0 + 8];
#pragma unroll
            for (int n = 0; n < 8; n++) {
                uint32_t bh0 = *(const uint32_t*)&Bh[buf][n * 8 + r0][kc * 16 + c0];
                uint32_t bh1 = *(const uint32_t*)&Bh[buf][n * 8 + r0][kc * 16 + c0 + 8];
                uint32_t bl0 = *(const uint32_t*)&Bl[buf][n * 8 + r0][kc * 16 + c0];
                uint32_t bl1 = *(const uint32_t*)&Bl[buf][n * 8 + r0][kc * 16 + c0 + 8];
                mma_bf16(s[n], ah, bh0, bh1);
                mma_bf16(s[n], ah, bl0, bl1);
                mma_bf16(s[n], al, bh0, bh1);
            }
        }
    }

    // epilogue
#pragma unroll
    for (int n = 0; n < 8; n++) {
#pragma unroll
        for (int j = 0; j < 4; j++) {
            int row = m0 + wid * 16 + r0 + (j >> 1) * 8;
            int col = n0 + n * 8 + c0 + (j & 1);
            float x = s[n][j] + Bv[col];
            int h = col >> 6, cc = col & 63;
            if (z == 0) {
                if (cc < 32) {
                    float v = x * SCALE;
                    split_store(v, &g_Qhi[h][row][cc], &g_Qlo[h][row][cc]);
                } else {
                    g_G[h][row][cc - 32] = 1.0f / (1.0f + __expf(-x));
                }
            } else {
                if (cc < 32) {
                    split_store(x, &g_Khi[h][row][cc], &g_Klo[h][row][cc]);
                } else {
                    split_store(x, &g_Vthi[h][cc - 32][row], &g_Vtlo[h][cc - 32][row]);
                }
            }
        }
    }
}

// =============== kernel 2: flash attention, split-K x2, bias cp.async pipeline ===============
#define ATTN_SMEM 54272
__global__ __launch_bounds__(128, 4) void attn_kernel(const float* __restrict__ bias)
{
    extern __shared__ __align__(16) char dynsm[];
    __nv_bfloat16 (*Kh)[40] = (__nv_bfloat16(*)[40])(dynsm);
    __nv_bfloat16 (*Kl)[40] = (__nv_bfloat16(*)[40])(dynsm + 5120);
    __nv_bfloat16 (*Vh)[72] = (__nv_bfloat16(*)[72])(dynsm + 10240);
    __nv_bfloat16 (*Vl)[72] = (__nv_bfloat16(*)[72])(dynsm + 14848);
    float* biasS = (float*)(dynsm + 19456);
#define BIASS(s, r, c) biasS[((s) * 64 + (r)) * 68 + (c)]

    const int h = blockIdx.y;
    const int z = blockIdx.z;
    const int tid = threadIdx.x, wid = tid >> 5, ln = tid & 31;
    const int q0b = blockIdx.x * 64;
    const int q0 = q0b + wid * 16;
    const int r0 = ln >> 2, c0 = (ln & 3) * 2;

    auto load_kv = [&](int kt) {
#pragma unroll
        for (int p = 0; p < 2; p++) {
            int e = tid + p * 128, r = e >> 2, c = (e & 3) * 8;
            cp_async16(smaddr(&Kh[r][c]), &g_Khi[h][kt + r][c]);
            cp_async16(smaddr(&Kl[r][c]), &g_Klo[h][kt + r][c]);
        }
#pragma unroll
        for (int p = 0; p < 2; p++) {
            int e = tid + p * 128, r = e >> 3, c = (e & 7) * 8;
            cp_async16(smaddr(&Vh[r][c]), &g_Vthi[h][r][kt + c]);
            cp_async16(smaddr(&Vl[r][c]), &g_Vtlo[h][r][kt + c]);
        }
    };
    auto load_bias = [&](int s, int kt) {
#pragma unroll
        for (int p = 0; p < 8; p++) {
            int e = tid + p * 128, r = e >> 4, seg = e & 15;
            cp_async16(smaddr(&BIASS(s, r, seg * 4)),
                       &bias[(size_t)(h * SLEN + q0b + r) * SLEN + kt + seg * 4]);
        }
    };

    uint32_t qh[2][4], ql[2][4];
#pragma unroll
    for (int kc = 0; kc < 2; kc++) {
        qh[kc][0] = *(const uint32_t*)&g_Qhi[h][q0 + r0][kc * 16 + c0];
        qh[kc][1] = *(const uint32_t*)&g_Qhi[h][q0 + r0 + 8][kc * 16 + c0];
        qh[kc][2] = *(const uint32_t*)&g_Qhi[h][q0 + r0][kc * 16 + c0 + 8];
        qh[kc][3] = *(const uint32_t*)&g_Qhi[h][q0 + r0 + 8][kc * 16 + c0 + 8];
        ql[kc][0] = *(const uint32_t*)&g_Qlo[h][q0 + r0][kc * 16 + c0];
        ql[kc][1] = *(const uint32_t*)&g_Qlo[h][q0 + r0 + 8][kc * 16 + c0];
        ql[kc][2] = *(const uint32_t*)&g_Qlo[h][q0 + r0][kc * 16 + c0 + 8];
        ql[kc][3] = *(const uint32_t*)&g_Qlo[h][q0 + r0 + 8][kc * 16 + c0 + 8];
    }

    float o[4][4];
#pragma unroll
    for (int n = 0; n < 4; n++)
#pragma unroll
        for (int j = 0; j < 4; j++) o[n][j] = 0.0f;
    float mr[2] = { -1e30f, -1e30f };
    float lr[2] = { 0.0f, 0.0f };

    load_bias(0, z * 64); cp_commit();

    const int NIT = SLEN / 64 / NSPLIT;   // 16
    for (int it = 0; it < NIT; it++) {
        const int kt = (it * NSPLIT + z) * 64;
        const int bbuf = it & 1;
        __syncthreads();
        load_kv(kt); cp_commit();
        if (it + 1 < NIT) { load_bias(bbuf ^ 1, kt + NSPLIT * 64); cp_commit(); }
        if (it + 1 < NIT) cp_wait<1>(); else cp_wait<0>();
        __syncthreads();

        float s[8][4];
#pragma unroll
        for (int n = 0; n < 8; n++) {
            s[n][0] = s[n][1] = s[n][2] = s[n][3] = 0.0f;
#pragma unroll
            for (int kc = 0; kc < 2; kc++) {
                uint32_t bh0 = *(const uint32_t*)&Kh[n * 8 + r0][kc * 16 + c0];
                uint32_t bh1 = *(const uint32_t*)&Kh[n * 8 + r0][kc * 16 + c0 + 8];
                uint32_t bl0 = *(const uint32_t*)&Kl[n * 8 + r0][kc * 16 + c0];
                uint32_t bl1 = *(const uint32_t*)&Kl[n * 8 + r0][kc * 16 + c0 + 8];
                mma_bf16(s[n], qh[kc], bh0, bh1);
                mma_bf16(s[n], qh[kc], bl0, bl1);
                mma_bf16(s[n], ql[kc], bh0, bh1);
            }
        }
        float mx[2] = { -1e30f, -1e30f };
        const int br0 = wid * 16 + r0;
#pragma unroll
        for (int n = 0; n < 8; n++) {
            float2 b0 = *(const float2*)&BIASS(bbuf, br0, n * 8 + c0);
            float2 b1 = *(const float2*)&BIASS(bbuf, br0 + 8, n * 8 + c0);
            s[n][0] += b0.x; s[n][1] += b0.y;
            s[n][2] += b1.x; s[n][3] += b1.y;
            mx[0] = fmaxf(mx[0], fmaxf(s[n][0], s[n][1]));
            mx[1] = fmaxf(mx[1], fmaxf(s[n][2], s[n][3]));
        }
#pragma unroll
        for (int i = 0; i < 2; i++) {
            mx[i] = fmaxf(mx[i], __shfl_xor_sync(0xffffffffu, mx[i], 1));
            mx[i] = fmaxf(mx[i], __shfl_xor_sync(0xffffffffu, mx[i], 2));
        }
        float mn[2] = { fmaxf(mr[0], mx[0]), fmaxf(mr[1], mx[1]) };
        float rs[2] = { ex2f((mr[0] - mn[0]) * LOG2E), ex2f((mr[1] - mn[1]) * LOG2E) };
        mr[0] = mn[0]; mr[1] = mn[1];
#pragma unroll
        for (int n = 0; n < 4; n++) {
            o[n][0] *= rs[0]; o[n][1] *= rs[0]; o[n][2] *= rs[1]; o[n][3] *= rs[1];
        }
        float sm[2] = { 0.0f, 0.0f };
#pragma unroll
        for (int n = 0; n < 8; n++)
#pragma unroll
            for (int j = 0; j < 4; j++) {
                float p = ex2f((s[n][j] - mn[j >> 1]) * LOG2E);
                s[n][j] = p;
                sm[j >> 1] += p;
            }
#pragma unroll
        for (int i = 0; i < 2; i++) {
            sm[i] += __shfl_xor_sync(0xffffffffu, sm[i], 1);
            sm[i] += __shfl_xor_sync(0xffffffffu, sm[i], 2);
            lr[i] = lr[i] * rs[i] + sm[i];
        }
        uint32_t ph[4][4], pl[4][4];
#pragma unroll
        for (int kc = 0; kc < 4; kc++) {
            splitp(s[2 * kc][0],     s[2 * kc][1],     ph[kc][0], pl[kc][0]);
            splitp(s[2 * kc][2],     s[2 * kc][3],     ph[kc][1], pl[kc][1]);
            splitp(s[2 * kc + 1][0], s[2 * kc + 1][1], ph[kc][2], pl[kc][2]);
            splitp(s[2 * kc + 1][2], s[2 * kc + 1][3], ph[kc][3], pl[kc][3]);
        }
#pragma unroll
        for (int n = 0; n < 4; n++)
#pragma unroll
            for (int kc = 0; kc < 4; kc++) {
                uint32_t vh0 = *(const uint32_t*)&Vh[n * 8 + r0][kc * 16 + c0];
                uint32_t vh1 = *(const uint32_t*)&Vh[n * 8 + r0][kc * 16 + c0 + 8];
                uint32_t vl0 = *(const uint32_t*)&Vl[n * 8 + r0][kc * 16 + c0];
                uint32_t vl1 = *(const uint32_t*)&Vl[n * 8 + r0][kc * 16 + c0 + 8];
                mma_bf16(o[n], ph[kc], vh0, vh1);
                mma_bf16(o[n], ph[kc], vl0, vl1);
                mma_bf16(o[n], pl[kc], vh0, vh1);
            }
    }
#pragma unroll
    for (int n = 0; n < 4; n++) {
        float2 w0 = { o[n][0], o[n][1] };
        float2 w1 = { o[n][2], o[n][3] };
        *(float2*)&g_Opart[z][h][q0 + r0][n * 8 + c0] = w0;
        *(float2*)&g_Opart[z][h][q0 + r0 + 8][n * 8 + c0] = w1;
    }
    if ((ln & 3) == 0) {
        g_ml[z][h][q0 + r0][0] = mr[0];
        g_ml[z][h][q0 + r0][1] = lr[0];
        g_ml[z][h][q0 + r0 + 8][0] = mr[1];
        g_ml[z][h][q0 + r0 + 8][1] = lr[1];
    }
#undef BIASS
}

// =============== kernel 2b: split-K merge + gate -> AO (bf16 split) ===============
__global__ __launch_bounds__(256) void merge_kernel()
{
    int t = blockIdx.x * 256 + threadIdx.x;   // one (h, q) row per thread
    int h = t >> 11, q = t & 2047;
    float m = -1e30f;
    float mv[NSPLIT], lv[NSPLIT];
#pragma unroll
    for (int p = 0; p < NSPLIT; p++) {
        mv[p] = g_ml[p][h][q][0];
        lv[p] = g_ml[p][h][q][1];
        m = fmaxf(m, mv[p]);
    }
    float a[NSPLIT], lsum = 0.0f;
#pragma unroll
    for (int p = 0; p < NSPLIT; p++) {
        a[p] = ex2f((mv[p] - m) * LOG2E);
        lsum += lv[p] * a[p];
    }
    float rl = 1.0f / lsum;
#pragma unroll
    for (int p = 0; p < NSPLIT; p++) a[p] *= rl;
#pragma unroll
    for (int c = 0; c < 32; c += 4) {
        float4 r = { 0.0f, 0.0f, 0.0f, 0.0f };
#pragma unroll
        for (int p = 0; p < NSPLIT; p++) {
            float4 x = *(const float4*)&g_Opart[p][h][q][c];
            r.x += x.x * a[p]; r.y += x.y * a[p];
            r.z += x.z * a[p]; r.w += x.w * a[p];
        }
        float4 gg = *(const float4*)&g_G[h][q][c];
        r.x *= gg.x; r.y *= gg.y; r.z *= gg.z; r.w *= gg.w;
        int base = q * 256 + h * 32 + c;
        split_store(r.x, &g_AOhi[base + 0], &g_AOlo[base + 0]);
        split_store(r.y, &g_AOhi[base + 1], &g_AOlo[base + 1]);
        split_store(r.z, &g_AOhi[base + 2], &g_AOlo[base + 2]);
        split_store(r.w, &g_AOhi[base + 3], &g_AOlo[base + 3]);
    }
}

// =============== kernel 3: output projection (split-bf16 MMA) ===============
__global__ __launch_bounds__(128) void outproj_mma(
    float* __restrict__ out, const float* __restrict__ Bv)
{
    __shared__ __align__(16) __nv_bfloat16 Ah[2][64][40], Al[2][64][40];
    __shared__ __align__(16) __nv_bfloat16 Bh[2][64][40], Bl[2][64][40];
    const int m0 = blockIdx.y * 64, n0 = blockIdx.x * 64;
    const int tid = threadIdx.x, wid = tid >> 5, ln = tid & 31;
    const int r0 = ln >> 2, c0 = (ln & 3) * 2;

    auto load_stage = [&](int s, int kt) {
#pragma unroll
        for (int p = 0; p < 2; p++) {
            int e = tid + p * 128, r = e >> 2, c = (e & 3) * 8;
            cp_async16(smaddr(&Ah[s][r][c]), &g_AOhi[(m0 + r) * 256 + kt + c]);
            cp_async16(smaddr(&Al[s][r][c]), &g_AOlo[(m0 + r) * 256 + kt + c]);
            cp_async16(smaddr(&Bh[s][r][c]), &g_Wothi[(n0 + r) * 256 + kt + c]);
            cp_async16(smaddr(&Bl[s][r][c]), &g_Wotlo[(n0 + r) * 256 + kt + c]);
        }
    };

    float s[8][4];
#pragma unroll
    for (int n = 0; n < 8; n++)
#pragma unroll
        for (int j = 0; j < 4; j++) s[n][j] = 0.0f;

    load_stage(0, 0); cp_commit();

    for (int it = 0; it < 8; it++) {
        const int buf = it & 1;
        cp_wait<0>();
        __syncthreads();
        if (it + 1 < 8) { load_stage(buf ^ 1, (it + 1) * 32); cp_commit(); }

#pragma unroll
        for (int kc = 0; kc < 2; kc++) {
            uint32_t ah[4], al[4];
            ah[0] = *(const uint32_t*)&Ah[buf][wid * 16 + r0][kc * 16 + c0];
            ah[1] = *(const uint32_t*)&Ah[buf][wid * 16 + r0 + 8][kc * 16 + c0];
            ah[2] = *(const uint32_t*)&Ah[buf][wid * 16 + r0][kc * 16 + c0 + 8];
            ah[3] = *(const uint32_t*)&Ah[buf][wid * 16 + r0 + 8][kc * 16 + c0 + 8];
            al[0] = *(const uint32_t*)&Al[buf][wid * 16 + r0][kc * 16 + c0];
            al[1] = *(const uint32_t*)&Al[buf][wid * 16 + r0 + 8][kc * 16 + c0];
            al[2] = *(const uint32_t*)&Al[buf][wid * 16 + r0][kc * 16 + c0 + 8];
            al[3] = *(const uint32_t*)&Al[buf][wid * 16 + r0 + 8][kc * 16 + c0 + 8];
#pragma unroll
            for (int n = 0; n < 8; n++) {
                uint32_t bh0 = *(const uint32_t*)&Bh[buf][n * 8 + r0][kc * 16 + c0];
                uint32_t bh1 = *(const uint32_t*)&Bh[buf][n * 8 + r0][kc * 16 + c0 + 8];
                uint32_t bl0 = *(const uint32_t*)&Bl[buf][n * 8 + r0][kc * 16 + c0];
                uint32_t bl1 = *(const uint32_t*)&Bl[buf][n * 8 + r0][kc * 16 + c0 + 8];
                mma_bf16(s[n], ah, bh0, bh1);
                mma_bf16(s[n], ah, bl0, bl1);
                mma_bf16(s[n], al, bh0, bh1);
            }
        }
    }

#pragma unroll
    for (int n = 0; n < 8; n++) {
#pragma unroll
        for (int half = 0; half < 2; half++) {
            int row = m0 + wid * 16 + r0 + half * 8;
            int col = n0 + n * 8 + c0;
            float2 v = { s[n][half * 2 + 0] + Bv[col], s[n][half * 2 + 1] + Bv[col + 1] };
            *(float2*)&out[row * 256 + col] = v;
        }
    }
}

// =============== launch ===============
extern "C" void kernel_launch(void* const* d_in, const int* in_sizes, int n_in,
                              void* d_out, int out_size) {
    const float* q_inputs   = (const float*)d_in[0];
    const float* kv_inputs  = (const float*)d_in[1];
    const float* bias       = (const float*)d_in[2];
    const float* qg_weights = (const float*)d_in[3];
    const float* kv_weights = (const float*)d_in[4];
    const float* qg_bias    = (const float*)d_in[5];
    const float* kv_bias    = (const float*)d_in[6];
    const float* o_weights  = (const float*)d_in[7];
    const float* o_bias     = (const float*)d_in[8];
    float* out = (float*)d_out;

    cudaFuncSetAttribute(attn_kernel, cudaFuncAttributeMaxDynamicSharedMemorySize, ATTN_SMEM);

    split_kernel<<<5376, 256>>>(q_inputs, kv_inputs, qg_weights, kv_weights, o_weights);
    proj_mma<<<dim3(8, 32, 2), 128>>>(qg_bias, kv_bias);
    attn_kernel<<<dim3(32, 8, NSPLIT), 128, ATTN_SMEM>>>(bias);
    merge_kernel<<<64, 256>>>();
    outproj_mma<<<dim3(4, 32), 128>>>(out, o_bias);
}

// round 10
// speedup vs baseline: 1.8719x; 1.0597x over previous
#include <cuda_runtime.h>
#include <cuda_bf16.h>
#include <stdint.h>

#define NHEAD 8
#define SLEN 2048
#define NSPLIT 2
#define SCALE 0.17677669529663689f
#define LOG2E 1.4426950408889634f

// ------------- device scratch (no allocation allowed) -------------
static __device__ __align__(16) __nv_bfloat16 g_Qhi[NHEAD][SLEN][32], g_Qlo[NHEAD][SLEN][32];
static __device__ __align__(16) __nv_bfloat16 g_Khi[NHEAD][SLEN][32], g_Klo[NHEAD][SLEN][32];
static __device__ __align__(16) __nv_bfloat16 g_Vthi[NHEAD][32][SLEN], g_Vtlo[NHEAD][32][SLEN];
static __device__ __align__(16) float g_G[NHEAD][SLEN][32];
static __device__ __align__(16) float g_Opart[NSPLIT][NHEAD][SLEN][32];
static __device__ __align__(16) float g_ml[NSPLIT][NHEAD][SLEN][2];
// split-bf16 inputs for MMA projections
static __device__ __align__(16) __nv_bfloat16 g_Xqhi[SLEN * 256], g_Xqlo[SLEN * 256];
static __device__ __align__(16) __nv_bfloat16 g_Xkhi[SLEN * 256], g_Xklo[SLEN * 256];
static __device__ __align__(16) __nv_bfloat16 g_Wqthi[512 * 256], g_Wqtlo[512 * 256];
static __device__ __align__(16) __nv_bfloat16 g_Wkthi[512 * 256], g_Wktlo[512 * 256];
static __device__ __align__(16) __nv_bfloat16 g_Wothi[256 * 256], g_Wotlo[256 * 256];
static __device__ __align__(16) __nv_bfloat16 g_AOhi[SLEN * 256], g_AOlo[SLEN * 256];

// ------------- helpers -------------
__device__ __forceinline__ float ex2f(float x) {
    float y; asm("ex2.approx.f32 %0, %1;" : "=f"(y) : "f"(x)); return y;
}
__device__ __forceinline__ uint32_t packbf(float lo, float hi) {
    uint32_t r; asm("cvt.rn.bf16x2.f32 %0, %1, %2;" : "=r"(r) : "f"(hi), "f"(lo)); return r;
}
__device__ __forceinline__ void splitp(float x, float y, uint32_t &hi, uint32_t &lo) {
    hi = packbf(x, y);
    float xh = __uint_as_float(hi << 16);
    float yh = __uint_as_float(hi & 0xffff0000u);
    lo = packbf(x - xh, y - yh);
}
__device__ __forceinline__ void mma_bf16(float* d, const uint32_t* a, uint32_t b0, uint32_t b1) {
    asm volatile("mma.sync.aligned.m16n8k16.row.col.f32.bf16.bf16.f32 "
        "{%0,%1,%2,%3},{%4,%5,%6,%7},{%8,%9},{%0,%1,%2,%3};"
        : "+f"(d[0]), "+f"(d[1]), "+f"(d[2]), "+f"(d[3])
        : "r"(a[0]), "r"(a[1]), "r"(a[2]), "r"(a[3]), "r"(b0), "r"(b1));
}
__device__ __forceinline__ uint32_t smaddr(const void* p) {
    return (uint32_t)__cvta_generic_to_shared(p);
}
__device__ __forceinline__ void ldsm4(uint32_t* r, const void* p) {
    uint32_t a = smaddr(p);
    asm volatile("ldmatrix.sync.aligned.m8n8.x4.shared.b16 {%0,%1,%2,%3},[%4];"
        : "=r"(r[0]), "=r"(r[1]), "=r"(r[2]), "=r"(r[3]) : "r"(a));
}
__device__ __forceinline__ void cp_async16(uint32_t s, const void* g) {
    asm volatile("cp.async.cg.shared.global [%0], [%1], 16;" :: "r"(s), "l"(g));
}
__device__ __forceinline__ void cp_commit() { asm volatile("cp.async.commit_group;"); }
template<int N> __device__ __forceinline__ void cp_wait() {
    asm volatile("cp.async.wait_group %0;" :: "n"(N));
}
__device__ __forceinline__ void split_store(float v, __nv_bfloat16* hi, __nv_bfloat16* lo) {
    __nv_bfloat16 h = __float2bfloat16(v);
    *hi = h;
    *lo = __float2bfloat16(v - __bfloat162float(h));
}

// =============== kernel 0: split/transposed-split prepass ===============
__global__ __launch_bounds__(256) void split_kernel(
    const float* __restrict__ Xq, const float* __restrict__ Xkv,
    const float* __restrict__ Wq, const float* __restrict__ Wk,
    const float* __restrict__ Wo)
{
    const int NX = SLEN * 256;     // 524288
    const int NW = 256 * 512;      // 131072
    const int NO = 256 * 256;      // 65536
    int i = blockIdx.x * 256 + threadIdx.x;
    if (i < NX) {
        split_store(Xq[i], &g_Xqhi[i], &g_Xqlo[i]);
    } else if (i < 2 * NX) {
        int j = i - NX;
        split_store(Xkv[j], &g_Xkhi[j], &g_Xklo[j]);
    } else if (i < 2 * NX + NW) {
        int j = i - 2 * NX;                 // j = n*256 + k
        int n = j >> 8, k = j & 255;
        split_store(Wq[k * 512 + n], &g_Wqthi[j], &g_Wqtlo[j]);
    } else if (i < 2 * NX + 2 * NW) {
        int j = i - 2 * NX - NW;
        int n = j >> 8, k = j & 255;
        split_store(Wk[k * 512 + n], &g_Wkthi[j], &g_Wktlo[j]);
    } else {
        int j = i - 2 * NX - 2 * NW;
        if (j < NO) {
            int n = j >> 8, k = j & 255;
            split_store(Wo[k * 256 + n], &g_Wothi[j], &g_Wotlo[j]);
        }
    }
}

// =============== kernel 1: input projections (split-bf16 MMA) ===============
__global__ __launch_bounds__(128) void proj_mma(
    const float* __restrict__ Bq, const float* __restrict__ Bk)
{
    __shared__ __align__(16) __nv_bfloat16 Ah[2][64][40], Al[2][64][40];
    __shared__ __align__(16) __nv_bfloat16 Bh[2][64][40], Bl[2][64][40];
    const int z = blockIdx.z;
    const __nv_bfloat16* __restrict__ Xhi  = z ? g_Xkhi  : g_Xqhi;
    const __nv_bfloat16* __restrict__ Xlo  = z ? g_Xklo  : g_Xqlo;
    const __nv_bfloat16* __restrict__ Wthi = z ? g_Wkthi : g_Wqthi;
    const __nv_bfloat16* __restrict__ Wtlo = z ? g_Wktlo : g_Wqtlo;
    const float* __restrict__ Bv = z ? Bk : Bq;
    const int m0 = blockIdx.y * 64, n0 = blockIdx.x * 64;
    const int tid = threadIdx.x, wid = tid >> 5, ln = tid & 31;
    const int r0 = ln >> 2, c0 = (ln & 3) * 2;

    auto load_stage = [&](int s, int kt) {
#pragma unroll
        for (int p = 0; p < 2; p++) {
            int e = tid + p * 128, r = e >> 2, c = (e & 3) * 8;
            cp_async16(smaddr(&Ah[s][r][c]), &Xhi[(m0 + r) * 256 + kt + c]);
            cp_async16(smaddr(&Al[s][r][c]), &Xlo[(m0 + r) * 256 + kt + c]);
            cp_async16(smaddr(&Bh[s][r][c]), &Wthi[(n0 + r) * 256 + kt + c]);
            cp_async16(smaddr(&Bl[s][r][c]), &Wtlo[(n0 + r) * 256 + kt + c]);
        }
    };

    float s[8][4];
#pragma unroll
    for (int n = 0; n < 8; n++)
#pragma unroll
        for (int j = 0; j < 4; j++) s[n][j] = 0.0f;

    load_stage(0, 0); cp_commit();

    for (int it = 0; it < 8; it++) {
        const int buf = it & 1;
        cp_wait<0>();
        __syncthreads();
        if (it + 1 < 8) { load_stage(buf ^ 1, (it + 1) * 32); cp_commit(); }

#pragma unroll
        for (int kc = 0; kc < 2; kc++) {
            uint32_t ah[4], al[4];
            ah[0] = *(const uint32_t*)&Ah[buf][wid * 16 + r0][kc * 16 + c0];
            ah[1] = *(const uint32_t*)&Ah[buf][wid * 16 + r0 + 8][kc * 16 + c0];
            ah[2] = *(const uint32_t*)&Ah[buf][wid * 16 + r0][kc * 16 + c0 + 8];
            ah[3] = *(const uint32_t*)&Ah[buf][wid * 16 + r0 + 8][kc * 16 + c0 + 8];
            al[0] = *(const uint32_t*)&Al[buf][wid * 16 + r0][kc * 16 + c0];
            al[1] = *(const uint32_t*)&Al[buf][wid * 16 + r0 + 8][kc * 16 + c0];
            al[2] = *(const uint32_t*)&Al[buf][wid * 16 + r0][kc * 16 + c0 + 8];
            al[3] = *(const uint32_t*)&Al[buf][wid * 16 + r0 + 8][kc * 16 + c0 + 8];
#pragma unroll
            for (int n = 0; n < 8; n++) {
                uint32_t bh0 = *(const uint32_t*)&Bh[buf][n * 8 + r0][kc * 16 + c0];
                uint32_t bh1 = *(const uint32_t*)&Bh[buf][n * 8 + r0][kc * 16 + c0 + 8];
                uint32_t bl0 = *(const uint32_t*)&Bl[buf][n * 8 + r0][kc * 16 + c0];
                uint32_t bl1 = *(const uint32_t*)&Bl[buf][n * 8 + r0][kc * 16 + c0 + 8];
                mma_bf16(s[n], ah, bh0, bh1);
                mma_bf16(s[n], ah, bl0, bl1);
                mma_bf16(s[n], al, bh0, bh1);
            }
        }
    }

    // epilogue
#pragma unroll
    for (int n = 0; n < 8; n++) {
#pragma unroll
        for (int j = 0; j < 4; j++) {
            int row = m0 + wid * 16 + r0 + (j >> 1) * 8;
            int col = n0 + n * 8 + c0 + (j & 1);
            float x = s[n][j] + Bv[col];
            int h = col >> 6, cc = col & 63;
            if (z == 0) {
                if (cc < 32) {
                    float v = x * SCALE;
                    split_store(v, &g_Qhi[h][row][cc], &g_Qlo[h][row][cc]);
                } else {
                    g_G[h][row][cc - 32] = 1.0f / (1.0f + __expf(-x));
                }
            } else {
                if (cc < 32) {
                    split_store(x, &g_Khi[h][row][cc], &g_Klo[h][row][cc]);
                } else {
                    split_store(x, &g_Vthi[h][cc - 32][row], &g_Vtlo[h][cc - 32][row]);
                }
            }
        }
    }
}

// =============== kernel 2: flash attention, split-K x2, bias cp.async pipeline ===============
#define ATTN_SMEM 54272
__global__ __launch_bounds__(128, 4) void attn_kernel(const float* __restrict__ bias)
{
    extern __shared__ __align__(16) char dynsm[];
    __nv_bfloat16 (*Kh)[40] = (__nv_bfloat16(*)[40])(dynsm);
    __nv_bfloat16 (*Kl)[40] = (__nv_bfloat16(*)[40])(dynsm + 5120);
    __nv_bfloat16 (*Vh)[72] = (__nv_bfloat16(*)[72])(dynsm + 10240);
    __nv_bfloat16 (*Vl)[72] = (__nv_bfloat16(*)[72])(dynsm + 14848);
    float* biasS = (float*)(dynsm + 19456);
#define BIASS(s, r, c) biasS[((s) * 64 + (r)) * 68 + (c)]

    const int h = blockIdx.y;
    const int z = blockIdx.z;
    const int tid = threadIdx.x, wid = tid >> 5, ln = tid & 31;
    const int q0b = blockIdx.x * 64;
    const int q0 = q0b + wid * 16;
    const int r0 = ln >> 2, c0 = (ln & 3) * 2;
    const int lr8 = ln & 7, lm = ln >> 3;   // ldmatrix addressing

    auto load_kv = [&](int kt) {
#pragma unroll
        for (int p = 0; p < 2; p++) {
            int e = tid + p * 128, r = e >> 2, c = (e & 3) * 8;
            cp_async16(smaddr(&Kh[r][c]), &g_Khi[h][kt + r][c]);
            cp_async16(smaddr(&Kl[r][c]), &g_Klo[h][kt + r][c]);
        }
#pragma unroll
        for (int p = 0; p < 2; p++) {
            int e = tid + p * 128, r = e >> 3, c = (e & 7) * 8;
            cp_async16(smaddr(&Vh[r][c]), &g_Vthi[h][r][kt + c]);
            cp_async16(smaddr(&Vl[r][c]), &g_Vtlo[h][r][kt + c]);
        }
    };
    auto load_bias = [&](int s, int kt) {
#pragma unroll
        for (int p = 0; p < 8; p++) {
            int e = tid + p * 128, r = e >> 4, seg = e & 15;
            cp_async16(smaddr(&BIASS(s, r, seg * 4)),
                       &bias[(size_t)(h * SLEN + q0b + r) * SLEN + kt + seg * 4]);
        }
    };

    uint32_t qh[2][4], ql[2][4];
#pragma unroll
    for (int kc = 0; kc < 2; kc++) {
        qh[kc][0] = *(const uint32_t*)&g_Qhi[h][q0 + r0][kc * 16 + c0];
        qh[kc][1] = *(const uint32_t*)&g_Qhi[h][q0 + r0 + 8][kc * 16 + c0];
        qh[kc][2] = *(const uint32_t*)&g_Qhi[h][q0 + r0][kc * 16 + c0 + 8];
        qh[kc][3] = *(const uint32_t*)&g_Qhi[h][q0 + r0 + 8][kc * 16 + c0 + 8];
        ql[kc][0] = *(const uint32_t*)&g_Qlo[h][q0 + r0][kc * 16 + c0];
        ql[kc][1] = *(const uint32_t*)&g_Qlo[h][q0 + r0 + 8][kc * 16 + c0];
        ql[kc][2] = *(const uint32_t*)&g_Qlo[h][q0 + r0][kc * 16 + c0 + 8];
        ql[kc][3] = *(const uint32_t*)&g_Qlo[h][q0 + r0 + 8][kc * 16 + c0 + 8];
    }

    float o[4][4];
#pragma unroll
    for (int n = 0; n < 4; n++)
#pragma unroll
        for (int j = 0; j < 4; j++) o[n][j] = 0.0f;
    float mr[2] = { -1e30f, -1e30f };
    float lr[2] = { 0.0f, 0.0f };

    load_bias(0, z * 64); cp_commit();

    const int NIT = SLEN / 64 / NSPLIT;   // 16
    for (int it = 0; it < NIT; it++) {
        const int kt = (it * NSPLIT + z) * 64;
        const int bbuf = it & 1;
        __syncthreads();
        load_kv(kt); cp_commit();
        if (it + 1 < NIT) { load_bias(bbuf ^ 1, kt + NSPLIT * 64); cp_commit(); }
        if (it + 1 < NIT) cp_wait<1>(); else cp_wait<0>();
        __syncthreads();

        // S = Q K^T (3-term split), K fragments via ldmatrix.x4
        float s[8][4];
#pragma unroll
        for (int n = 0; n < 8; n++) {
            s[n][0] = s[n][1] = s[n][2] = s[n][3] = 0.0f;
            uint32_t kh[4], kl[4];
            ldsm4(kh, &Kh[n * 8 + lr8][lm * 8]);
            ldsm4(kl, &Kl[n * 8 + lr8][lm * 8]);
            mma_bf16(s[n], qh[0], kh[0], kh[1]);
            mma_bf16(s[n], qh[0], kl[0], kl[1]);
            mma_bf16(s[n], ql[0], kh[0], kh[1]);
            mma_bf16(s[n], qh[1], kh[2], kh[3]);
            mma_bf16(s[n], qh[1], kl[2], kl[3]);
            mma_bf16(s[n], ql[1], kh[2], kh[3]);
        }
        float mx[2] = { -1e30f, -1e30f };
        const int br0 = wid * 16 + r0;
#pragma unroll
        for (int n = 0; n < 8; n++) {
            float2 b0 = *(const float2*)&BIASS(bbuf, br0, n * 8 + c0);
            float2 b1 = *(const float2*)&BIASS(bbuf, br0 + 8, n * 8 + c0);
            s[n][0] += b0.x; s[n][1] += b0.y;
            s[n][2] += b1.x; s[n][3] += b1.y;
            mx[0] = fmaxf(mx[0], fmaxf(s[n][0], s[n][1]));
            mx[1] = fmaxf(mx[1], fmaxf(s[n][2], s[n][3]));
        }
#pragma unroll
        for (int i = 0; i < 2; i++) {
            mx[i] = fmaxf(mx[i], __shfl_xor_sync(0xffffffffu, mx[i], 1));
            mx[i] = fmaxf(mx[i], __shfl_xor_sync(0xffffffffu, mx[i], 2));
        }
        float mn[2] = { fmaxf(mr[0], mx[0]), fmaxf(mr[1], mx[1]) };
        float rs[2] = { ex2f((mr[0] - mn[0]) * LOG2E), ex2f((mr[1] - mn[1]) * LOG2E) };
        mr[0] = mn[0]; mr[1] = mn[1];
#pragma unroll
        for (int n = 0; n < 4; n++) {
            o[n][0] *= rs[0]; o[n][1] *= rs[0]; o[n][2] *= rs[1]; o[n][3] *= rs[1];
        }
        float sm[2] = { 0.0f, 0.0f };
#pragma unroll
        for (int n = 0; n < 8; n++)
#pragma unroll
            for (int j = 0; j < 4; j++) {
                float p = ex2f((s[n][j] - mn[j >> 1]) * LOG2E);
                s[n][j] = p;
                sm[j >> 1] += p;
            }
#pragma unroll
        for (int i = 0; i < 2; i++) {
            sm[i] += __shfl_xor_sync(0xffffffffu, sm[i], 1);
            sm[i] += __shfl_xor_sync(0xffffffffu, sm[i], 2);
            lr[i] = lr[i] * rs[i] + sm[i];
        }
        uint32_t ph[4][4], pl[4][4];
#pragma unroll
        for (int kc = 0; kc < 4; kc++) {
            splitp(s[2 * kc][0],     s[2 * kc][1],     ph[kc][0], pl[kc][0]);
            splitp(s[2 * kc][2],     s[2 * kc][3],     ph[kc][1], pl[kc][1]);
            splitp(s[2 * kc + 1][0], s[2 * kc + 1][1], ph[kc][2], pl[kc][2]);
            splitp(s[2 * kc + 1][2], s[2 * kc + 1][3], ph[kc][3], pl[kc][3]);
        }
        // O += P V (3-term split), V fragments via ldmatrix.x4
#pragma unroll
        for (int n = 0; n < 4; n++) {
            uint32_t vh[8], vl[8];
            ldsm4(vh,     &Vh[n * 8 + lr8][lm * 8]);
            ldsm4(vh + 4, &Vh[n * 8 + lr8][32 + lm * 8]);
            ldsm4(vl,     &Vl[n * 8 + lr8][lm * 8]);
            ldsm4(vl + 4, &Vl[n * 8 + lr8][32 + lm * 8]);
#pragma unroll
            for (int kc = 0; kc < 4; kc++) {
                mma_bf16(o[n], ph[kc], vh[kc * 2], vh[kc * 2 + 1]);
                mma_bf16(o[n], ph[kc], vl[kc * 2], vl[kc * 2 + 1]);
                mma_bf16(o[n], pl[kc], vh[kc * 2], vh[kc * 2 + 1]);
            }
        }
    }
#pragma unroll
    for (int n = 0; n < 4; n++) {
        float2 w0 = { o[n][0], o[n][1] };
        float2 w1 = { o[n][2], o[n][3] };
        *(float2*)&g_Opart[z][h][q0 + r0][n * 8 + c0] = w0;
        *(float2*)&g_Opart[z][h][q0 + r0 + 8][n * 8 + c0] = w1;
    }
    if ((ln & 3) == 0) {
        g_ml[z][h][q0 + r0][0] = mr[0];
        g_ml[z][h][q0 + r0][1] = lr[0];
        g_ml[z][h][q0 + r0 + 8][0] = mr[1];
        g_ml[z][h][q0 + r0 + 8][1] = lr[1];
    }
#undef BIASS
}

// =============== kernel 2b: split-K merge + gate -> AO (bf16 split), coalesced ===============
__global__ __launch_bounds__(256) void merge_kernel()
{
    int t = blockIdx.x * 256 + threadIdx.x;   // 131072 threads: 8 per (h,q) row
    int row = t >> 3, cs = (t & 7) * 4;
    int h = row >> 11, q = row & 2047;
    float m = -1e30f;
    float mv[NSPLIT], lv[NSPLIT];
#pragma unroll
    for (int p = 0; p < NSPLIT; p++) {
        mv[p] = g_ml[p][h][q][0];
        lv[p] = g_ml[p][h][q][1];
        m = fmaxf(m, mv[p]);
    }
    float a[NSPLIT], lsum = 0.0f;
#pragma unroll
    for (int p = 0; p < NSPLIT; p++) {
        a[p] = ex2f((mv[p] - m) * LOG2E);
        lsum += lv[p] * a[p];
    }
    float rl = 1.0f / lsum;
#pragma unroll
    for (int p = 0; p < NSPLIT; p++) a[p] *= rl;

    float4 r = { 0.0f, 0.0f, 0.0f, 0.0f };
#pragma unroll
    for (int p = 0; p < NSPLIT; p++) {
        float4 x = *(const float4*)&g_Opart[p][h][q][cs];
        r.x += x.x * a[p]; r.y += x.y * a[p];
        r.z += x.z * a[p]; r.w += x.w * a[p];
    }
    float4 gg = *(const float4*)&g_G[h][q][cs];
    r.x *= gg.x; r.y *= gg.y; r.z *= gg.z; r.w *= gg.w;
    uint32_t h01, l01, h23, l23;
    splitp(r.x, r.y, h01, l01);
    splitp(r.z, r.w, h23, l23);
    int base = q * 256 + h * 32 + cs;
    *(uint2*)&g_AOhi[base] = make_uint2(h01, h23);
    *(uint2*)&g_AOlo[base] = make_uint2(l01, l23);
}

// =============== kernel 3: output projection (split-bf16 MMA) ===============
__global__ __launch_bounds__(128) void outproj_mma(
    float* __restrict__ out, const float* __restrict__ Bv)
{
    __shared__ __align__(16) __nv_bfloat16 Ah[2][64][40], Al[2][64][40];
    __shared__ __align__(16) __nv_bfloat16 Bh[2][64][40], Bl[2][64][40];
    const int m0 = blockIdx.y * 64, n0 = blockIdx.x * 64;
    const int tid = threadIdx.x, wid = tid >> 5, ln = tid & 31;
    const int r0 = ln >> 2, c0 = (ln & 3) * 2;

    auto load_stage = [&](int s, int kt) {
#pragma unroll
        for (int p = 0; p < 2; p++) {
            int e = tid + p * 128, r = e >> 2, c = (e & 3) * 8;
            cp_async16(smaddr(&Ah[s][r][c]), &g_AOhi[(m0 + r) * 256 + kt + c]);
            cp_async16(smaddr(&Al[s][r][c]), &g_AOlo[(m0 + r) * 256 + kt + c]);
            cp_async16(smaddr(&Bh[s][r][c]), &g_Wothi[(n0 + r) * 256 + kt + c]);
            cp_async16(smaddr(&Bl[s][r][c]), &g_Wotlo[(n0 + r) * 256 + kt + c]);
        }
    };

    float s[8][4];
#pragma unroll
    for (int n = 0; n < 8; n++)
#pragma unroll
        for (int j = 0; j < 4; j++) s[n][j] = 0.0f;

    load_stage(0, 0); cp_commit();

    for (int it = 0; it < 8; it++) {
        const int buf = it & 1;
        cp_wait<0>();
        __syncthreads();
        if (it + 1 < 8) { load_stage(buf ^ 1, (it + 1) * 32); cp_commit(); }

#pragma unroll
        for (int kc = 0; kc < 2; kc++) {
            uint32_t ah[4], al[4];
            ah[0] = *(const uint32_t*)&Ah[buf][wid * 16 + r0][kc * 16 + c0];
            ah[1] = *(const uint32_t*)&Ah[buf][wid * 16 + r0 + 8][kc * 16 + c0];
            ah[2] = *(const uint32_t*)&Ah[buf][wid * 16 + r0][kc * 16 + c0 + 8];
            ah[3] = *(const uint32_t*)&Ah[buf][wid * 16 + r0 + 8][kc * 16 + c0 + 8];
            al[0] = *(const uint32_t*)&Al[buf][wid * 16 + r0][kc * 16 + c0];
            al[1] = *(const uint32_t*)&Al[buf][wid * 16 + r0 + 8][kc * 16 + c0];
            al[2] = *(const uint32_t*)&Al[buf][wid * 16 + r0][kc * 16 + c0 + 8];
            al[3] = *(const uint32_t*)&Al[buf][wid * 16 + r0 + 8][kc * 16 + c0 + 8];
#pragma unroll
            for (int n = 0; n < 8; n++) {
                uint32_t bh0 = *(const uint32_t*)&Bh[buf][n * 8 + r0][kc * 16 + c0];
                uint32_t bh1 = *(const uint32_t*)&Bh[buf][n * 8 + r0][kc * 16 + c0 + 8];
                uint32_t bl0 = *(const uint32_t*)&Bl[buf][n * 8 + r0][kc * 16 + c0];
                uint32_t bl1 = *(const uint32_t*)&Bl[buf][n * 8 + r0][kc * 16 + c0 + 8];
                mma_bf16(s[n], ah, bh0, bh1);
                mma_bf16(s[n], ah, bl0, bl1);
                mma_bf16(s[n], al, bh0, bh1);
            }
        }
    }

#pragma unroll
    for (int n = 0; n < 8; n++) {
#pragma unroll
        for (int half = 0; half < 2; half++) {
            int row = m0 + wid * 16 + r0 + half * 8;
            int col = n0 + n * 8 + c0;
            float2 v = { s[n][half * 2 + 0] + Bv[col], s[n][half * 2 + 1] + Bv[col + 1] };
            *(float2*)&out[row * 256 + col] = v;
        }
    }
}

// =============== launch ===============
extern "C" void kernel_launch(void* const* d_in, const int* in_sizes, int n_in,
                              void* d_out, int out_size) {
    const float* q_inputs   = (const float*)d_in[0];
    const float* kv_inputs  = (const float*)d_in[1];
    const float* bias       = (const float*)d_in[2];
    const float* qg_weights = (const float*)d_in[3];
    const float* kv_weights = (const float*)d_in[4];
    const float* qg_bias    = (const float*)d_in[5];
    const float* kv_bias    = (const float*)d_in[6];
    const float* o_weights  = (const float*)d_in[7];
    const float* o_bias     = (const float*)d_in[8];
    float* out = (float*)d_out;

    cudaFuncSetAttribute(attn_kernel, cudaFuncAttributeMaxDynamicSharedMemorySize, ATTN_SMEM);

    split_kernel<<<5376, 256>>>(q_inputs, kv_inputs, qg_weights, kv_weights, o_weights);
    proj_mma<<<dim3(8, 32, 2), 128>>>(qg_bias, kv_bias);
    attn_kernel<<<dim3(32, 8, NSPLIT), 128, ATTN_SMEM>>>(bias);
    merge_kernel<<<512, 256>>>();
    outproj_mma<<<dim3(4, 32), 128>>>(out, o_bias);
}

// round 11
// speedup vs baseline: 2.1756x; 1.1623x over previous
#include <cuda_runtime.h>
#include <cuda_bf16.h>
#include <cuda_fp16.h>
#include <stdint.h>

#define NHEAD 8
#define SLEN 2048
#define NSPLIT 2
#define SCALE 0.17677669529663689f
#define LOG2E 1.4426950408889634f

// ------------- device scratch (no allocation allowed) -------------
static __device__ __align__(16) __half g_Qh[NHEAD][SLEN][32], g_Ql[NHEAD][SLEN][32];
static __device__ __align__(16) __half g_Kh[NHEAD][SLEN][32];
static __device__ __align__(16) __half g_Vth[NHEAD][32][SLEN], g_Vtl[NHEAD][32][SLEN];
static __device__ __align__(16) float g_G[NHEAD][SLEN][32];
static __device__ __align__(16) float g_Opart[NSPLIT][NHEAD][SLEN][32];
static __device__ __align__(16) float g_ml[NSPLIT][NHEAD][SLEN][2];
// split-bf16 inputs for MMA projections
static __device__ __align__(16) __nv_bfloat16 g_Xqhi[SLEN * 256], g_Xqlo[SLEN * 256];
static __device__ __align__(16) __nv_bfloat16 g_Xkhi[SLEN * 256], g_Xklo[SLEN * 256];
static __device__ __align__(16) __nv_bfloat16 g_Wqthi[512 * 256], g_Wqtlo[512 * 256];
static __device__ __align__(16) __nv_bfloat16 g_Wkthi[512 * 256], g_Wktlo[512 * 256];
static __device__ __align__(16) __nv_bfloat16 g_Wothi[256 * 256], g_Wotlo[256 * 256];
static __device__ __align__(16) __nv_bfloat16 g_AOhi[SLEN * 256], g_AOlo[SLEN * 256];

// ------------- helpers -------------
__device__ __forceinline__ float ex2f(float x) {
    float y; asm("ex2.approx.f32 %0, %1;" : "=f"(y) : "f"(x)); return y;
}
__device__ __forceinline__ uint32_t packbf(float lo, float hi) {
    uint32_t r; asm("cvt.rn.bf16x2.f32 %0, %1, %2;" : "=r"(r) : "f"(hi), "f"(lo)); return r;
}
__device__ __forceinline__ uint32_t packh(float lo, float hi) {
    uint32_t r; asm("cvt.rn.f16x2.f32 %0, %1, %2;" : "=r"(r) : "f"(hi), "f"(lo)); return r;
}
__device__ __forceinline__ void splitp(float x, float y, uint32_t &hi, uint32_t &lo) {
    hi = packbf(x, y);
    float xh = __uint_as_float(hi << 16);
    float yh = __uint_as_float(hi & 0xffff0000u);
    lo = packbf(x - xh, y - yh);
}
__device__ __forceinline__ void mma_bf16(float* d, const uint32_t* a, uint32_t b0, uint32_t b1) {
    asm volatile("mma.sync.aligned.m16n8k16.row.col.f32.bf16.bf16.f32 "
        "{%0,%1,%2,%3},{%4,%5,%6,%7},{%8,%9},{%0,%1,%2,%3};"
        : "+f"(d[0]), "+f"(d[1]), "+f"(d[2]), "+f"(d[3])
        : "r"(a[0]), "r"(a[1]), "r"(a[2]), "r"(a[3]), "r"(b0), "r"(b1));
}
__device__ __forceinline__ void mma_f16(float* d, const uint32_t* a, uint32_t b0, uint32_t b1) {
    asm volatile("mma.sync.aligned.m16n8k16.row.col.f32.f16.f16.f32 "
        "{%0,%1,%2,%3},{%4,%5,%6,%7},{%8,%9},{%0,%1,%2,%3};"
        : "+f"(d[0]), "+f"(d[1]), "+f"(d[2]), "+f"(d[3])
        : "r"(a[0]), "r"(a[1]), "r"(a[2]), "r"(a[3]), "r"(b0), "r"(b1));
}
__device__ __forceinline__ uint32_t smaddr(const void* p) {
    return (uint32_t)__cvta_generic_to_shared(p);
}
__device__ __forceinline__ void ldsm4(uint32_t* r, const void* p) {
    uint32_t a = smaddr(p);
    asm volatile("ldmatrix.sync.aligned.m8n8.x4.shared.b16 {%0,%1,%2,%3},[%4];"
        : "=r"(r[0]), "=r"(r[1]), "=r"(r[2]), "=r"(r[3]) : "r"(a));
}
__device__ __forceinline__ void cp_async16(uint32_t s, const void* g) {
    asm volatile("cp.async.cg.shared.global [%0], [%1], 16;" :: "r"(s), "l"(g));
}
__device__ __forceinline__ void cp_commit() { asm volatile("cp.async.commit_group;"); }
template<int N> __device__ __forceinline__ void cp_wait() {
    asm volatile("cp.async.wait_group %0;" :: "n"(N));
}
__device__ __forceinline__ void split_store(float v, __nv_bfloat16* hi, __nv_bfloat16* lo) {
    __nv_bfloat16 h = __float2bfloat16(v);
    *hi = h;
    *lo = __float2bfloat16(v - __bfloat162float(h));
}
__device__ __forceinline__ void split_store_h(float v, __half* hi, __half* lo) {
    __half h = __float2half(v);
    *hi = h;
    *lo = __float2half(v - __half2float(h));
}

// =============== kernel 0: split/transposed-split prepass ===============
__global__ __launch_bounds__(256) void split_kernel(
    const float* __restrict__ Xq, const float* __restrict__ Xkv,
    const float* __restrict__ Wq, const float* __restrict__ Wk,
    const float* __restrict__ Wo)
{
    const int NX = SLEN * 256;     // 524288
    const int NW = 256 * 512;      // 131072
    const int NO = 256 * 256;      // 65536
    int i = blockIdx.x * 256 + threadIdx.x;
    if (i < NX) {
        split_store(Xq[i], &g_Xqhi[i], &g_Xqlo[i]);
    } else if (i < 2 * NX) {
        int j = i - NX;
        split_store(Xkv[j], &g_Xkhi[j], &g_Xklo[j]);
    } else if (i < 2 * NX + NW) {
        int j = i - 2 * NX;                 // j = n*256 + k
        int n = j >> 8, k = j & 255;
        split_store(Wq[k * 512 + n], &g_Wqthi[j], &g_Wqtlo[j]);
    } else if (i < 2 * NX + 2 * NW) {
        int j = i - 2 * NX - NW;
        int n = j >> 8, k = j & 255;
        split_store(Wk[k * 512 + n], &g_Wkthi[j], &g_Wktlo[j]);
    } else {
        int j = i - 2 * NX - 2 * NW;
        if (j < NO) {
            int n = j >> 8, k = j & 255;
            split_store(Wo[k * 256 + n], &g_Wothi[j], &g_Wotlo[j]);
        }
    }
}

// =============== kernel 1: input projections (split-bf16 MMA) ===============
__global__ __launch_bounds__(128) void proj_mma(
    const float* __restrict__ Bq, const float* __restrict__ Bk)
{
    __shared__ __align__(16) __nv_bfloat16 Ah[2][64][40], Al[2][64][40];
    __shared__ __align__(16) __nv_bfloat16 Bh[2][64][40], Bl[2][64][40];
    const int z = blockIdx.z;
    const __nv_bfloat16* __restrict__ Xhi  = z ? g_Xkhi  : g_Xqhi;
    const __nv_bfloat16* __restrict__ Xlo  = z ? g_Xklo  : g_Xqlo;
    const __nv_bfloat16* __restrict__ Wthi = z ? g_Wkthi : g_Wqthi;
    const __nv_bfloat16* __restrict__ Wtlo = z ? g_Wktlo : g_Wqtlo;
    const float* __restrict__ Bv = z ? Bk : Bq;
    const int m0 = blockIdx.y * 64, n0 = blockIdx.x * 64;
    const int tid = threadIdx.x, wid = tid >> 5, ln = tid & 31;
    const int r0 = ln >> 2, c0 = (ln & 3) * 2;

    auto load_stage = [&](int s, int kt) {
#pragma unroll
        for (int p = 0; p < 2; p++) {
            int e = tid + p * 128, r = e >> 2, c = (e & 3) * 8;
            cp_async16(smaddr(&Ah[s][r][c]), &Xhi[(m0 + r) * 256 + kt + c]);
            cp_async16(smaddr(&Al[s][r][c]), &Xlo[(m0 + r) * 256 + kt + c]);
            cp_async16(smaddr(&Bh[s][r][c]), &Wthi[(n0 + r) * 256 + kt + c]);
            cp_async16(smaddr(&Bl[s][r][c]), &Wtlo[(n0 + r) * 256 + kt + c]);
        }
    };

    float s[8][4];
#pragma unroll
    for (int n = 0; n < 8; n++)
#pragma unroll
        for (int j = 0; j < 4; j++) s[n][j] = 0.0f;

    load_stage(0, 0); cp_commit();

    for (int it = 0; it < 8; it++) {
        const int buf = it & 1;
        cp_wait<0>();
        __syncthreads();
        if (it + 1 < 8) { load_stage(buf ^ 1, (it + 1) * 32); cp_commit(); }

#pragma unroll
        for (int kc = 0; kc < 2; kc++) {
            uint32_t ah[4], al[4];
            ah[0] = *(const uint32_t*)&Ah[buf][wid * 16 + r0][kc * 16 + c0];
            ah[1] = *(const uint32_t*)&Ah[buf][wid * 16 + r0 + 8][kc * 16 + c0];
            ah[2] = *(const uint32_t*)&Ah[buf][wid * 16 + r0][kc * 16 + c0 + 8];
            ah[3] = *(const uint32_t*)&Ah[buf][wid * 16 + r0 + 8][kc * 16 + c0 + 8];
            al[0] = *(const uint32_t*)&Al[buf][wid * 16 + r0][kc * 16 + c0];
            al[1] = *(const uint32_t*)&Al[buf][wid * 16 + r0 + 8][kc * 16 + c0];
            al[2] = *(const uint32_t*)&Al[buf][wid * 16 + r0][kc * 16 + c0 + 8];
            al[3] = *(const uint32_t*)&Al[buf][wid * 16 + r0 + 8][kc * 16 + c0 + 8];
#pragma unroll
            for (int n = 0; n < 8; n++) {
                uint32_t bh0 = *(const uint32_t*)&Bh[buf][n * 8 + r0][kc * 16 + c0];
                uint32_t bh1 = *(const uint32_t*)&Bh[buf][n * 8 + r0][kc * 16 + c0 + 8];
                uint32_t bl0 = *(const uint32_t*)&Bl[buf][n * 8 + r0][kc * 16 + c0];
                uint32_t bl1 = *(const uint32_t*)&Bl[buf][n * 8 + r0][kc * 16 + c0 + 8];
                mma_bf16(s[n], ah, bh0, bh1);
                mma_bf16(s[n], ah, bl0, bl1);
                mma_bf16(s[n], al, bh0, bh1);
            }
        }
    }

    // epilogue: write Q (fp16 split), K (fp16), V (fp16 split, transposed), G (fp32)
#pragma unroll
    for (int n = 0; n < 8; n++) {
#pragma unroll
        for (int j = 0; j < 4; j++) {
            int row = m0 + wid * 16 + r0 + (j >> 1) * 8;
            int col = n0 + n * 8 + c0 + (j & 1);
            float x = s[n][j] + Bv[col];
            int h = col >> 6, cc = col & 63;
            if (z == 0) {
                if (cc < 32) {
                    float v = x * SCALE;
                    split_store_h(v, &g_Qh[h][row][cc], &g_Ql[h][row][cc]);
                } else {
                    g_G[h][row][cc - 32] = 1.0f / (1.0f + __expf(-x));
                }
            } else {
                if (cc < 32) {
                    g_Kh[h][row][cc] = __float2half(x);
                } else {
                    split_store_h(x, &g_Vth[h][cc - 32][row], &g_Vtl[h][cc - 32][row]);
                }
            }
        }
    }
}

// =============== kernel 2: flash attention (fp16 MMA), split-K x2, bias pipeline ===============
// dynamic smem layout (bytes):
//   Kh: 64x40 half            @ 0       (5120)
//   Vh: 32x72 half            @ 5120    (4608)
//   Vl: 32x72 half            @ 9728    (4608)
//   Bias: 2 stages x 64x68 f32 @ 14336  (34816)   total = 49152
#define ATTN_SMEM 49152
__global__ __launch_bounds__(128, 4) void attn_kernel(const float* __restrict__ bias)
{
    extern __shared__ __align__(16) char dynsm[];
    __half (*Kh)[40] = (__half(*)[40])(dynsm);
    __half (*Vh)[72] = (__half(*)[72])(dynsm + 5120);
    __half (*Vl)[72] = (__half(*)[72])(dynsm + 9728);
    float* biasS = (float*)(dynsm + 14336);
#define BIASS(s, r, c) biasS[((s) * 64 + (r)) * 68 + (c)]

    const int h = blockIdx.y;
    const int z = blockIdx.z;
    const int tid = threadIdx.x, wid = tid >> 5, ln = tid & 31;
    const int q0b = blockIdx.x * 64;
    const int q0 = q0b + wid * 16;
    const int r0 = ln >> 2, c0 = (ln & 3) * 2;
    const int lr8 = ln & 7, lm = ln >> 3;   // ldmatrix addressing

    auto load_kv = [&](int kt) {
#pragma unroll
        for (int p = 0; p < 2; p++) {
            int e = tid + p * 128, r = e >> 2, c = (e & 3) * 8;   // 8 halves = 16B
            cp_async16(smaddr(&Kh[r][c]), &g_Kh[h][kt + r][c]);
        }
#pragma unroll
        for (int p = 0; p < 2; p++) {
            int e = tid + p * 128, r = e >> 3, c = (e & 7) * 8;   // 8 halves = 16B
            cp_async16(smaddr(&Vh[r][c]), &g_Vth[h][r][kt + c]);
            cp_async16(smaddr(&Vl[r][c]), &g_Vtl[h][r][kt + c]);
        }
    };
    auto load_bias = [&](int s, int kt) {
#pragma unroll
        for (int p = 0; p < 8; p++) {
            int e = tid + p * 128, r = e >> 4, seg = e & 15;
            cp_async16(smaddr(&BIASS(s, r, seg * 4)),
                       &bias[(size_t)(h * SLEN + q0b + r) * SLEN + kt + seg * 4]);
        }
    };

    // Q fragments (hi/lo fp16), 2 k-chunks of 16
    uint32_t qh[2][4], ql[2][4];
#pragma unroll
    for (int kc = 0; kc < 2; kc++) {
        qh[kc][0] = *(const uint32_t*)&g_Qh[h][q0 + r0][kc * 16 + c0];
        qh[kc][1] = *(const uint32_t*)&g_Qh[h][q0 + r0 + 8][kc * 16 + c0];
        qh[kc][2] = *(const uint32_t*)&g_Qh[h][q0 + r0][kc * 16 + c0 + 8];
        qh[kc][3] = *(const uint32_t*)&g_Qh[h][q0 + r0 + 8][kc * 16 + c0 + 8];
        ql[kc][0] = *(const uint32_t*)&g_Ql[h][q0 + r0][kc * 16 + c0];
        ql[kc][1] = *(const uint32_t*)&g_Ql[h][q0 + r0 + 8][kc * 16 + c0];
        ql[kc][2] = *(const uint32_t*)&g_Ql[h][q0 + r0][kc * 16 + c0 + 8];
        ql[kc][3] = *(const uint32_t*)&g_Ql[h][q0 + r0 + 8][kc * 16 + c0 + 8];
    }

    float o[4][4];
#pragma unroll
    for (int n = 0; n < 4; n++)
#pragma unroll
        for (int j = 0; j < 4; j++) o[n][j] = 0.0f;
    float mr[2] = { -1e30f, -1e30f };
    float lr[2] = { 0.0f, 0.0f };

    load_bias(0, z * 64); cp_commit();

    const int NIT = SLEN / 64 / NSPLIT;   // 16
    for (int it = 0; it < NIT; it++) {
        const int kt = (it * NSPLIT + z) * 64;
        const int bbuf = it & 1;
        __syncthreads();
        load_kv(kt); cp_commit();
        if (it + 1 < NIT) { load_bias(bbuf ^ 1, kt + NSPLIT * 64); cp_commit(); }
        if (it + 1 < NIT) cp_wait<1>(); else cp_wait<0>();
        __syncthreads();

        // S = Q K^T :  (qh + ql) . kh   (2 MMAs per kc, K single fp16)
        float s[8][4];
#pragma unroll
        for (int n = 0; n < 8; n++) {
            s[n][0] = s[n][1] = s[n][2] = s[n][3] = 0.0f;
            uint32_t kh[4];
            ldsm4(kh, &Kh[n * 8 + lr8][lm * 8]);
            mma_f16(s[n], qh[0], kh[0], kh[1]);
            mma_f16(s[n], ql[0], kh[0], kh[1]);
            mma_f16(s[n], qh[1], kh[2], kh[3]);
            mma_f16(s[n], ql[1], kh[2], kh[3]);
        }
        float mx[2] = { -1e30f, -1e30f };
        const int br0 = wid * 16 + r0;
#pragma unroll
        for (int n = 0; n < 8; n++) {
            float2 b0 = *(const float2*)&BIASS(bbuf, br0, n * 8 + c0);
            float2 b1 = *(const float2*)&BIASS(bbuf, br0 + 8, n * 8 + c0);
            s[n][0] += b0.x; s[n][1] += b0.y;
            s[n][2] += b1.x; s[n][3] += b1.y;
            mx[0] = fmaxf(mx[0], fmaxf(s[n][0], s[n][1]));
            mx[1] = fmaxf(mx[1], fmaxf(s[n][2], s[n][3]));
        }
#pragma unroll
        for (int i = 0; i < 2; i++) {
            mx[i] = fmaxf(mx[i], __shfl_xor_sync(0xffffffffu, mx[i], 1));
            mx[i] = fmaxf(mx[i], __shfl_xor_sync(0xffffffffu, mx[i], 2));
        }
        float mn[2] = { fmaxf(mr[0], mx[0]), fmaxf(mr[1], mx[1]) };
        float rs[2] = { ex2f((mr[0] - mn[0]) * LOG2E), ex2f((mr[1] - mn[1]) * LOG2E) };
        mr[0] = mn[0]; mr[1] = mn[1];
#pragma unroll
        for (int n = 0; n < 4; n++) {
            o[n][0] *= rs[0]; o[n][1] *= rs[0]; o[n][2] *= rs[1]; o[n][3] *= rs[1];
        }
        float sm[2] = { 0.0f, 0.0f };
#pragma unroll
        for (int n = 0; n < 8; n++)
#pragma unroll
            for (int j = 0; j < 4; j++) {
                float p = ex2f((s[n][j] - mn[j >> 1]) * LOG2E);
                s[n][j] = p;
                sm[j >> 1] += p;
            }
#pragma unroll
        for (int i = 0; i < 2; i++) {
            sm[i] += __shfl_xor_sync(0xffffffffu, sm[i], 1);
            sm[i] += __shfl_xor_sync(0xffffffffu, sm[i], 2);
            lr[i] = lr[i] * rs[i] + sm[i];
        }
        // pack P into single fp16 A-fragments (no split)
        uint32_t ph[4][4];
#pragma unroll
        for (int kc = 0; kc < 4; kc++) {
            ph[kc][0] = packh(s[2 * kc][0],     s[2 * kc][1]);
            ph[kc][1] = packh(s[2 * kc][2],     s[2 * kc][3]);
            ph[kc][2] = packh(s[2 * kc + 1][0], s[2 * kc + 1][1]);
            ph[kc][3] = packh(s[2 * kc + 1][2], s[2 * kc + 1][3]);
        }
        // O += P V :  p . (vh + vl)  (2 MMAs per kc)
#pragma unroll
        for (int n = 0; n < 4; n++) {
            uint32_t vh[8], vl[8];
            ldsm4(vh,     &Vh[n * 8 + lr8][lm * 8]);
            ldsm4(vh + 4, &Vh[n * 8 + lr8][32 + lm * 8]);
            ldsm4(vl,     &Vl[n * 8 + lr8][lm * 8]);
            ldsm4(vl + 4, &Vl[n * 8 + lr8][32 + lm * 8]);
#pragma unroll
            for (int kc = 0; kc < 4; kc++) {
                mma_f16(o[n], ph[kc], vh[kc * 2], vh[kc * 2 + 1]);
                mma_f16(o[n], ph[kc], vl[kc * 2], vl[kc * 2 + 1]);
            }
        }
    }
#pragma unroll
    for (int n = 0; n < 4; n++) {
        float2 w0 = { o[n][0], o[n][1] };
        float2 w1 = { o[n][2], o[n][3] };
        *(float2*)&g_Opart[z][h][q0 + r0][n * 8 + c0] = w0;
        *(float2*)&g_Opart[z][h][q0 + r0 + 8][n * 8 + c0] = w1;
    }
    if ((ln & 3) == 0) {
        g_ml[z][h][q0 + r0][0] = mr[0];
        g_ml[z][h][q0 + r0][1] = lr[0];
        g_ml[z][h][q0 + r0 + 8][0] = mr[1];
        g_ml[z][h][q0 + r0 + 8][1] = lr[1];
    }
#undef BIASS
}

// =============== kernel 2b: split-K merge + gate -> AO (bf16 split), coalesced ===============
__global__ __launch_bounds__(256) void merge_kernel()
{
    int t = blockIdx.x * 256 + threadIdx.x;   // 131072 threads: 8 per (h,q) row
    int row = t >> 3, cs = (t & 7) * 4;
    int h = row >> 11, q = row & 2047;
    float m = -1e30f;
    float mv[NSPLIT], lv[NSPLIT];
#pragma unroll
    for (int p = 0; p < NSPLIT; p++) {
        mv[p] = g_ml[p][h][q][0];
        lv[p] = g_ml[p][h][q][1];
        m = fmaxf(m, mv[p]);
    }
    float a[NSPLIT], lsum = 0.0f;
#pragma unroll
    for (int p = 0; p < NSPLIT; p++) {
        a[p] = ex2f((mv[p] - m) * LOG2E);
        lsum += lv[p] * a[p];
    }
    float rl = 1.0f / lsum;
#pragma unroll
    for (int p = 0; p < NSPLIT; p++) a[p] *= rl;

    float4 r = { 0.0f, 0.0f, 0.0f, 0.0f };
#pragma unroll
    for (int p = 0; p < NSPLIT; p++) {
        float4 x = *(const float4*)&g_Opart[p][h][q][cs];
        r.x += x.x * a[p]; r.y += x.y * a[p];
        r.z += x.z * a[p]; r.w += x.w * a[p];
    }
    float4 gg = *(const float4*)&g_G[h][q][cs];
    r.x *= gg.x; r.y *= gg.y; r.z *= gg.z; r.w *= gg.w;
    uint32_t h01, l01, h23, l23;
    splitp(r.x, r.y, h01, l01);
    splitp(r.z, r.w, h23, l23);
    int base = q * 256 + h * 32 + cs;
    *(uint2*)&g_AOhi[base] = make_uint2(h01, h23);
    *(uint2*)&g_AOlo[base] = make_uint2(l01, l23);
}

// =============== kernel 3: output projection (split-bf16 MMA) ===============
__global__ __launch_bounds__(128) void outproj_mma(
    float* __restrict__ out, const float* __restrict__ Bv)
{
    __shared__ __align__(16) __nv_bfloat16 Ah[2][64][40], Al[2][64][40];
    __shared__ __align__(16) __nv_bfloat16 Bh[2][64][40], Bl[2][64][40];
    const int m0 = blockIdx.y * 64, n0 = blockIdx.x * 64;
    const int tid = threadIdx.x, wid = tid >> 5, ln = tid & 31;
    const int r0 = ln >> 2, c0 = (ln & 3) * 2;

    auto load_stage = [&](int s, int kt) {
#pragma unroll
        for (int p = 0; p < 2; p++) {
            int e = tid + p * 128, r = e >> 2, c = (e & 3) * 8;
            cp_async16(smaddr(&Ah[s][r][c]), &g_AOhi[(m0 + r) * 256 + kt + c]);
            cp_async16(smaddr(&Al[s][r][c]), &g_AOlo[(m0 + r) * 256 + kt + c]);
            cp_async16(smaddr(&Bh[s][r][c]), &g_Wothi[(n0 + r) * 256 + kt + c]);
            cp_async16(smaddr(&Bl[s][r][c]), &g_Wotlo[(n0 + r) * 256 + kt + c]);
        }
    };

    float s[8][4];
#pragma unroll
    for (int n = 0; n < 8; n++)
#pragma unroll
        for (int j = 0; j < 4; j++) s[n][j] = 0.0f;

    load_stage(0, 0); cp_commit();

    for (int it = 0; it < 8; it++) {
        const int buf = it & 1;
        cp_wait<0>();
        __syncthreads();
        if (it + 1 < 8) { load_stage(buf ^ 1, (it + 1) * 32); cp_commit(); }

#pragma unroll
        for (int kc = 0; kc < 2; kc++) {
            uint32_t ah[4], al[4];
            ah[0] = *(const uint32_t*)&Ah[buf][wid * 16 + r0][kc * 16 + c0];
            ah[1] = *(const uint32_t*)&Ah[buf][wid * 16 + r0 + 8][kc * 16 + c0];
            ah[2] = *(const uint32_t*)&Ah[buf][wid * 16 + r0][kc * 16 + c0 + 8];
            ah[3] = *(const uint32_t*)&Ah[buf][wid * 16 + r0 + 8][kc * 16 + c0 + 8];
            al[0] = *(const uint32_t*)&Al[buf][wid * 16 + r0][kc * 16 + c0];
            al[1] = *(const uint32_t*)&Al[buf][wid * 16 + r0 + 8][kc * 16 + c0];
            al[2] = *(const uint32_t*)&Al[buf][wid * 16 + r0][kc * 16 + c0 + 8];
            al[3] = *(const uint32_t*)&Al[buf][wid * 16 + r0 + 8][kc * 16 + c0 + 8];
#pragma unroll
            for (int n = 0; n < 8; n++) {
                uint32_t bh0 = *(const uint32_t*)&Bh[buf][n * 8 + r0][kc * 16 + c0];
                uint32_t bh1 = *(const uint32_t*)&Bh[buf][n * 8 + r0][kc * 16 + c0 + 8];
                uint32_t bl0 = *(const uint32_t*)&Bl[buf][n * 8 + r0][kc * 16 + c0];
                uint32_t bl1 = *(const uint32_t*)&Bl[buf][n * 8 + r0][kc * 16 + c0 + 8];
                mma_bf16(s[n], ah, bh0, bh1);
                mma_bf16(s[n], ah, bl0, bl1);
                mma_bf16(s[n], al, bh0, bh1);
            }
        }
    }

#pragma unroll
    for (int n = 0; n < 8; n++) {
#pragma unroll
        for (int half = 0; half < 2; half++) {
            int row = m0 + wid * 16 + r0 + half * 8;
            int col = n0 + n * 8 + c0;
            float2 v = { s[n][half * 2 + 0] + Bv[col], s[n][half * 2 + 1] + Bv[col + 1] };
            *(float2*)&out[row * 256 + col] = v;
        }
    }
}

// =============== launch ===============
extern "C" void kernel_launch(void* const* d_in, const int* in_sizes, int n_in,
                              void* d_out, int out_size) {
    const float* q_inputs   = (const float*)d_in[0];
    const float* kv_inputs  = (const float*)d_in[1];
    const float* bias       = (const float*)d_in[2];
    const float* qg_weights = (const float*)d_in[3];
    const float* kv_weights = (const float*)d_in[4];
    const float* qg_bias    = (const float*)d_in[5];
    const float* kv_bias    = (const float*)d_in[6];
    const float* o_weights  = (const float*)d_in[7];
    const float* o_bias     = (const float*)d_in[8];
    float* out = (float*)d_out;

    cudaFuncSetAttribute(attn_kernel, cudaFuncAttributeMaxDynamicSharedMemorySize, ATTN_SMEM);

    split_kernel<<<5376, 256>>>(q_inputs, kv_inputs, qg_weights, kv_weights, o_weights);
    proj_mma<<<dim3(8, 32, 2), 128>>>(qg_bias, kv_bias);
    attn_kernel<<<dim3(32, 8, NSPLIT), 128, ATTN_SMEM>>>(bias);
    merge_kernel<<<512, 256>>>();
    outproj_mma<<<dim3(4, 32), 128>>>(out, o_bias);
}

// round 12
// speedup vs baseline: 2.4070x; 1.1064x over previous
#include <cuda_runtime.h>
#include <cuda_bf16.h>
#include <cuda_fp16.h>
#include <stdint.h>

#define NHEAD 8
#define SLEN 2048
#define NSPLIT 2
#define SCALE 0.17677669529663689f
#define LOG2E 1.4426950408889634f

// ------------- device scratch (no allocation allowed) -------------
static __device__ __align__(16) __half g_Qh[NHEAD][SLEN][32];
static __device__ __align__(16) __half g_Kh[NHEAD][SLEN][32];
static __device__ __align__(16) __half g_Vth[NHEAD][32][SLEN];
static __device__ __align__(16) float g_G[NHEAD][SLEN][32];
static __device__ __align__(16) float g_Opart[NSPLIT][NHEAD][SLEN][32];
static __device__ __align__(16) float g_ml[NSPLIT][NHEAD][SLEN][2];
// split-bf16 inputs for MMA projections
static __device__ __align__(16) __nv_bfloat16 g_Xqhi[SLEN * 256], g_Xqlo[SLEN * 256];
static __device__ __align__(16) __nv_bfloat16 g_Xkhi[SLEN * 256], g_Xklo[SLEN * 256];
static __device__ __align__(16) __nv_bfloat16 g_Wqthi[512 * 256], g_Wqtlo[512 * 256];
static __device__ __align__(16) __nv_bfloat16 g_Wkthi[512 * 256], g_Wktlo[512 * 256];
static __device__ __align__(16) __nv_bfloat16 g_Wothi[256 * 256], g_Wotlo[256 * 256];
static __device__ __align__(16) __nv_bfloat16 g_AOhi[SLEN * 256], g_AOlo[SLEN * 256];

// ------------- helpers -------------
__device__ __forceinline__ float ex2f(float x) {
    float y; asm("ex2.approx.f32 %0, %1;" : "=f"(y) : "f"(x)); return y;
}
__device__ __forceinline__ uint32_t packbf(float lo, float hi) {
    uint32_t r; asm("cvt.rn.bf16x2.f32 %0, %1, %2;" : "=r"(r) : "f"(hi), "f"(lo)); return r;
}
__device__ __forceinline__ uint32_t packh(float lo, float hi) {
    uint32_t r; asm("cvt.rn.f16x2.f32 %0, %1, %2;" : "=r"(r) : "f"(hi), "f"(lo)); return r;
}
__device__ __forceinline__ void splitp(float x, float y, uint32_t &hi, uint32_t &lo) {
    hi = packbf(x, y);
    float xh = __uint_as_float(hi << 16);
    float yh = __uint_as_float(hi & 0xffff0000u);
    lo = packbf(x - xh, y - yh);
}
__device__ __forceinline__ void mma_bf16(float* d, const uint32_t* a, uint32_t b0, uint32_t b1) {
    asm volatile("mma.sync.aligned.m16n8k16.row.col.f32.bf16.bf16.f32 "
        "{%0,%1,%2,%3},{%4,%5,%6,%7},{%8,%9},{%0,%1,%2,%3};"
        : "+f"(d[0]), "+f"(d[1]), "+f"(d[2]), "+f"(d[3])
        : "r"(a[0]), "r"(a[1]), "r"(a[2]), "r"(a[3]), "r"(b0), "r"(b1));
}
__device__ __forceinline__ void mma_f16(float* d, const uint32_t* a, uint32_t b0, uint32_t b1) {
    asm volatile("mma.sync.aligned.m16n8k16.row.col.f32.f16.f16.f32 "
        "{%0,%1,%2,%3},{%4,%5,%6,%7},{%8,%9},{%0,%1,%2,%3};"
        : "+f"(d[0]), "+f"(d[1]), "+f"(d[2]), "+f"(d[3])
        : "r"(a[0]), "r"(a[1]), "r"(a[2]), "r"(a[3]), "r"(b0), "r"(b1));
}
__device__ __forceinline__ uint32_t smaddr(const void* p) {
    return (uint32_t)__cvta_generic_to_shared(p);
}
__device__ __forceinline__ void ldsm4(uint32_t* r, const void* p) {
    uint32_t a = smaddr(p);
    asm volatile("ldmatrix.sync.aligned.m8n8.x4.shared.b16 {%0,%1,%2,%3},[%4];"
        : "=r"(r[0]), "=r"(r[1]), "=r"(r[2]), "=r"(r[3]) : "r"(a));
}
__device__ __forceinline__ void cp_async16(uint32_t s, const void* g) {
    asm volatile("cp.async.cg.shared.global [%0], [%1], 16;" :: "r"(s), "l"(g));
}
__device__ __forceinline__ void cp_commit() { asm volatile("cp.async.commit_group;"); }
template<int N> __device__ __forceinline__ void cp_wait() {
    asm volatile("cp.async.wait_group %0;" :: "n"(N));
}
__device__ __forceinline__ void split_store(float v, __nv_bfloat16* hi, __nv_bfloat16* lo) {
    __nv_bfloat16 h = __float2bfloat16(v);
    *hi = h;
    *lo = __float2bfloat16(v - __bfloat162float(h));
}

// =============== kernel 0: split/transposed-split prepass ===============
__global__ __launch_bounds__(256) void split_kernel(
    const float* __restrict__ Xq, const float* __restrict__ Xkv,
    const float* __restrict__ Wq, const float* __restrict__ Wk,
    const float* __restrict__ Wo)
{
    const int NX = SLEN * 256;     // 524288
    const int NW = 256 * 512;      // 131072
    const int NO = 256 * 256;      // 65536
    int i = blockIdx.x * 256 + threadIdx.x;
    if (i < NX) {
        split_store(Xq[i], &g_Xqhi[i], &g_Xqlo[i]);
    } else if (i < 2 * NX) {
        int j = i - NX;
        split_store(Xkv[j], &g_Xkhi[j], &g_Xklo[j]);
    } else if (i < 2 * NX + NW) {
        int j = i - 2 * NX;                 // j = n*256 + k
        int n = j >> 8, k = j & 255;
        split_store(Wq[k * 512 + n], &g_Wqthi[j], &g_Wqtlo[j]);
    } else if (i < 2 * NX + 2 * NW) {
        int j = i - 2 * NX - NW;
        int n = j >> 8, k = j & 255;
        split_store(Wk[k * 512 + n], &g_Wkthi[j], &g_Wktlo[j]);
    } else {
        int j = i - 2 * NX - 2 * NW;
        if (j < NO) {
            int n = j >> 8, k = j & 255;
            split_store(Wo[k * 256 + n], &g_Wothi[j], &g_Wotlo[j]);
        }
    }
}

// =============== kernel 1: input projections (split-bf16 MMA) ===============
__global__ __launch_bounds__(128) void proj_mma(
    const float* __restrict__ Bq, const float* __restrict__ Bk)
{
    __shared__ __align__(16) __nv_bfloat16 Ah[2][64][40], Al[2][64][40];
    __shared__ __align__(16) __nv_bfloat16 Bh[2][64][40], Bl[2][64][40];
    const int z = blockIdx.z;
    const __nv_bfloat16* __restrict__ Xhi  = z ? g_Xkhi  : g_Xqhi;
    const __nv_bfloat16* __restrict__ Xlo  = z ? g_Xklo  : g_Xqlo;
    const __nv_bfloat16* __restrict__ Wthi = z ? g_Wkthi : g_Wqthi;
    const __nv_bfloat16* __restrict__ Wtlo = z ? g_Wktlo : g_Wqtlo;
    const float* __restrict__ Bv = z ? Bk : Bq;
    const int m0 = blockIdx.y * 64, n0 = blockIdx.x * 64;
    const int tid = threadIdx.x, wid = tid >> 5, ln = tid & 31;
    const int r0 = ln >> 2, c0 = (ln & 3) * 2;

    auto load_stage = [&](int s, int kt) {
#pragma unroll
        for (int p = 0; p < 2; p++) {
            int e = tid + p * 128, r = e >> 2, c = (e & 3) * 8;
            cp_async16(smaddr(&Ah[s][r][c]), &Xhi[(m0 + r) * 256 + kt + c]);
            cp_async16(smaddr(&Al[s][r][c]), &Xlo[(m0 + r) * 256 + kt + c]);
            cp_async16(smaddr(&Bh[s][r][c]), &Wthi[(n0 + r) * 256 + kt + c]);
            cp_async16(smaddr(&Bl[s][r][c]), &Wtlo[(n0 + r) * 256 + kt + c]);
        }
    };

    float s[8][4];
#pragma unroll
    for (int n = 0; n < 8; n++)
#pragma unroll
        for (int j = 0; j < 4; j++) s[n][j] = 0.0f;

    load_stage(0, 0); cp_commit();

    for (int it = 0; it < 8; it++) {
        const int buf = it & 1;
        cp_wait<0>();
        __syncthreads();
        if (it + 1 < 8) { load_stage(buf ^ 1, (it + 1) * 32); cp_commit(); }

#pragma unroll
        for (int kc = 0; kc < 2; kc++) {
            uint32_t ah[4], al[4];
            ah[0] = *(const uint32_t*)&Ah[buf][wid * 16 + r0][kc * 16 + c0];
            ah[1] = *(const uint32_t*)&Ah[buf][wid * 16 + r0 + 8][kc * 16 + c0];
            ah[2] = *(const uint32_t*)&Ah[buf][wid * 16 + r0][kc * 16 + c0 + 8];
            ah[3] = *(const uint32_t*)&Ah[buf][wid * 16 + r0 + 8][kc * 16 + c0 + 8];
            al[0] = *(const uint32_t*)&Al[buf][wid * 16 + r0][kc * 16 + c0];
            al[1] = *(const uint32_t*)&Al[buf][wid * 16 + r0 + 8][kc * 16 + c0];
            al[2] = *(const uint32_t*)&Al[buf][wid * 16 + r0][kc * 16 + c0 + 8];
            al[3] = *(const uint32_t*)&Al[buf][wid * 16 + r0 + 8][kc * 16 + c0 + 8];
#pragma unroll
            for (int n = 0; n < 8; n++) {
                uint32_t bh0 = *(const uint32_t*)&Bh[buf][n * 8 + r0][kc * 16 + c0];
                uint32_t bh1 = *(const uint32_t*)&Bh[buf][n * 8 + r0][kc * 16 + c0 + 8];
                uint32_t bl0 = *(const uint32_t*)&Bl[buf][n * 8 + r0][kc * 16 + c0];
                uint32_t bl1 = *(const uint32_t*)&Bl[buf][n * 8 + r0][kc * 16 + c0 + 8];
                mma_bf16(s[n], ah, bh0, bh1);
                mma_bf16(s[n], ah, bl0, bl1);
                mma_bf16(s[n], al, bh0, bh1);
            }
        }
    }

    // epilogue: write Q (fp16), K (fp16), V (fp16, transposed), G (fp32)
#pragma unroll
    for (int n = 0; n < 8; n++) {
#pragma unroll
        for (int j = 0; j < 4; j++) {
            int row = m0 + wid * 16 + r0 + (j >> 1) * 8;
            int col = n0 + n * 8 + c0 + (j & 1);
            float x = s[n][j] + Bv[col];
            int h = col >> 6, cc = col & 63;
            if (z == 0) {
                if (cc < 32) {
                    g_Qh[h][row][cc] = __float2half(x * SCALE);
                } else {
                    g_G[h][row][cc - 32] = 1.0f / (1.0f + __expf(-x));
                }
            } else {
                if (cc < 32) {
                    g_Kh[h][row][cc] = __float2half(x);
                } else {
                    g_Vth[h][cc - 32][row] = __float2half(x);
                }
            }
        }
    }
}

// =============== kernel 2: flash attention (fp16 MMA), split-K x2, bias pipeline ===============
// dynamic smem layout (bytes):
//   Kh: 64x40 half            @ 0       (5120)
//   Vh: 32x72 half            @ 5120    (4608)
//   Bias: 2 stages x 64x68 f32 @ 9728   (34816)   total = 44544
#define ATTN_SMEM 44544
__global__ __launch_bounds__(128, 4) void attn_kernel(const float* __restrict__ bias)
{
    extern __shared__ __align__(16) char dynsm[];
    __half (*Kh)[40] = (__half(*)[40])(dynsm);
    __half (*Vh)[72] = (__half(*)[72])(dynsm + 5120);
    float* biasS = (float*)(dynsm + 9728);
#define BIASS(s, r, c) biasS[((s) * 64 + (r)) * 68 + (c)]

    const int h = blockIdx.y;
    const int z = blockIdx.z;
    const int tid = threadIdx.x, wid = tid >> 5, ln = tid & 31;
    const int q0b = blockIdx.x * 64;
    const int q0 = q0b + wid * 16;
    const int r0 = ln >> 2, c0 = (ln & 3) * 2;
    const int lr8 = ln & 7, lm = ln >> 3;   // ldmatrix addressing

    auto load_kv = [&](int kt) {
#pragma unroll
        for (int p = 0; p < 2; p++) {
            int e = tid + p * 128, r = e >> 2, c = (e & 3) * 8;   // 8 halves = 16B
            cp_async16(smaddr(&Kh[r][c]), &g_Kh[h][kt + r][c]);
        }
#pragma unroll
        for (int p = 0; p < 2; p++) {
            int e = tid + p * 128, r = e >> 3, c = (e & 7) * 8;   // 8 halves = 16B
            cp_async16(smaddr(&Vh[r][c]), &g_Vth[h][r][kt + c]);
        }
    };
    auto load_bias = [&](int s, int kt) {
#pragma unroll
        for (int p = 0; p < 8; p++) {
            int e = tid + p * 128, r = e >> 4, seg = e & 15;
            cp_async16(smaddr(&BIASS(s, r, seg * 4)),
                       &bias[(size_t)(h * SLEN + q0b + r) * SLEN + kt + seg * 4]);
        }
    };

    // Q fragments (single fp16), 2 k-chunks of 16
    uint32_t qh[2][4];
#pragma unroll
    for (int kc = 0; kc < 2; kc++) {
        qh[kc][0] = *(const uint32_t*)&g_Qh[h][q0 + r0][kc * 16 + c0];
        qh[kc][1] = *(const uint32_t*)&g_Qh[h][q0 + r0 + 8][kc * 16 + c0];
        qh[kc][2] = *(const uint32_t*)&g_Qh[h][q0 + r0][kc * 16 + c0 + 8];
        qh[kc][3] = *(const uint32_t*)&g_Qh[h][q0 + r0 + 8][kc * 16 + c0 + 8];
    }

    float o[4][4];
#pragma unroll
    for (int n = 0; n < 4; n++)
#pragma unroll
        for (int j = 0; j < 4; j++) o[n][j] = 0.0f;
    float mr[2] = { -1e30f, -1e30f };
    float lr[2] = { 0.0f, 0.0f };

    load_bias(0, z * 64); cp_commit();

    const int NIT = SLEN / 64 / NSPLIT;   // 16
    for (int it = 0; it < NIT; it++) {
        const int kt = (it * NSPLIT + z) * 64;
        const int bbuf = it & 1;
        __syncthreads();
        load_kv(kt); cp_commit();
        if (it + 1 < NIT) { load_bias(bbuf ^ 1, kt + NSPLIT * 64); cp_commit(); }
        if (it + 1 < NIT) cp_wait<1>(); else cp_wait<0>();
        __syncthreads();

        // S = Q K^T  (single fp16 both sides, 2 MMAs per n-tile)
        float s[8][4];
#pragma unroll
        for (int n = 0; n < 8; n++) {
            s[n][0] = s[n][1] = s[n][2] = s[n][3] = 0.0f;
            uint32_t kh[4];
            ldsm4(kh, &Kh[n * 8 + lr8][lm * 8]);
            mma_f16(s[n], qh[0], kh[0], kh[1]);
            mma_f16(s[n], qh[1], kh[2], kh[3]);
        }
        float mx[2] = { -1e30f, -1e30f };
        const int br0 = wid * 16 + r0;
#pragma unroll
        for (int n = 0; n < 8; n++) {
            float2 b0 = *(const float2*)&BIASS(bbuf, br0, n * 8 + c0);
            float2 b1 = *(const float2*)&BIASS(bbuf, br0 + 8, n * 8 + c0);
            s[n][0] += b0.x; s[n][1] += b0.y;
            s[n][2] += b1.x; s[n][3] += b1.y;
            mx[0] = fmaxf(mx[0], fmaxf(s[n][0], s[n][1]));
            mx[1] = fmaxf(mx[1], fmaxf(s[n][2], s[n][3]));
        }
#pragma unroll
        for (int i = 0; i < 2; i++) {
            mx[i] = fmaxf(mx[i], __shfl_xor_sync(0xffffffffu, mx[i], 1));
            mx[i] = fmaxf(mx[i], __shfl_xor_sync(0xffffffffu, mx[i], 2));
        }
        float mn[2] = { fmaxf(mr[0], mx[0]), fmaxf(mr[1], mx[1]) };
        float rs[2] = { ex2f((mr[0] - mn[0]) * LOG2E), ex2f((mr[1] - mn[1]) * LOG2E) };
        mr[0] = mn[0]; mr[1] = mn[1];
#pragma unroll
        for (int n = 0; n < 4; n++) {
            o[n][0] *= rs[0]; o[n][1] *= rs[0]; o[n][2] *= rs[1]; o[n][3] *= rs[1];
        }
        float sm[2] = { 0.0f, 0.0f };
#pragma unroll
        for (int n = 0; n < 8; n++)
#pragma unroll
            for (int j = 0; j < 4; j++) {
                float p = ex2f((s[n][j] - mn[j >> 1]) * LOG2E);
                s[n][j] = p;
                sm[j >> 1] += p;
            }
#pragma unroll
        for (int i = 0; i < 2; i++) {
            sm[i] += __shfl_xor_sync(0xffffffffu, sm[i], 1);
            sm[i] += __shfl_xor_sync(0xffffffffu, sm[i], 2);
            lr[i] = lr[i] * rs[i] + sm[i];
        }
        // pack P into single fp16 A-fragments
        uint32_t ph[4][4];
#pragma unroll
        for (int kc = 0; kc < 4; kc++) {
            ph[kc][0] = packh(s[2 * kc][0],     s[2 * kc][1]);
            ph[kc][1] = packh(s[2 * kc][2],     s[2 * kc][3]);
            ph[kc][2] = packh(s[2 * kc + 1][0], s[2 * kc + 1][1]);
            ph[kc][3] = packh(s[2 * kc + 1][2], s[2 * kc + 1][3]);
        }
        // O += P V  (single fp16 V, 4 MMAs per n-tile)
#pragma unroll
        for (int n = 0; n < 4; n++) {
            uint32_t vh[8];
            ldsm4(vh,     &Vh[n * 8 + lr8][lm * 8]);
            ldsm4(vh + 4, &Vh[n * 8 + lr8][32 + lm * 8]);
#pragma unroll
            for (int kc = 0; kc < 4; kc++) {
                mma_f16(o[n], ph[kc], vh[kc * 2], vh[kc * 2 + 1]);
            }
        }
    }
#pragma unroll
    for (int n = 0; n < 4; n++) {
        float2 w0 = { o[n][0], o[n][1] };
        float2 w1 = { o[n][2], o[n][3] };
        *(float2*)&g_Opart[z][h][q0 + r0][n * 8 + c0] = w0;
        *(float2*)&g_Opart[z][h][q0 + r0 + 8][n * 8 + c0] = w1;
    }
    if ((ln & 3) == 0) {
        g_ml[z][h][q0 + r0][0] = mr[0];
        g_ml[z][h][q0 + r0][1] = lr[0];
        g_ml[z][h][q0 + r0 + 8][0] = mr[1];
        g_ml[z][h][q0 + r0 + 8][1] = lr[1];
    }
#undef BIASS
}

// =============== kernel 2b: split-K merge + gate -> AO (bf16 split), coalesced ===============
__global__ __launch_bounds__(256) void merge_kernel()
{
    int t = blockIdx.x * 256 + threadIdx.x;   // 131072 threads: 8 per (h,q) row
    int row = t >> 3, cs = (t & 7) * 4;
    int h = row >> 11, q = row & 2047;
    float m = -1e30f;
    float mv[NSPLIT], lv[NSPLIT];
#pragma unroll
    for (int p = 0; p < NSPLIT; p++) {
        mv[p] = g_ml[p][h][q][0];
        lv[p] = g_ml[p][h][q][1];
        m = fmaxf(m, mv[p]);
    }
    float a[NSPLIT], lsum = 0.0f;
#pragma unroll
    for (int p = 0; p < NSPLIT; p++) {
        a[p] = ex2f((mv[p] - m) * LOG2E);
        lsum += lv[p] * a[p];
    }
    float rl = 1.0f / lsum;
#pragma unroll
    for (int p = 0; p < NSPLIT; p++) a[p] *= rl;

    float4 r = { 0.0f, 0.0f, 0.0f, 0.0f };
#pragma unroll
    for (int p = 0; p < NSPLIT; p++) {
        float4 x = *(const float4*)&g_Opart[p][h][q][cs];
        r.x += x.x * a[p]; r.y += x.y * a[p];
        r.z += x.z * a[p]; r.w += x.w * a[p];
    }
    float4 gg = *(const float4*)&g_G[h][q][cs];
    r.x *= gg.x; r.y *= gg.y; r.z *= gg.z; r.w *= gg.w;
    uint32_t h01, l01, h23, l23;
    splitp(r.x, r.y, h01, l01);
    splitp(r.z, r.w, h23, l23);
    int base = q * 256 + h * 32 + cs;
    *(uint2*)&g_AOhi[base] = make_uint2(h01, h23);
    *(uint2*)&g_AOlo[base] = make_uint2(l01, l23);
}

// =============== kernel 3: output projection (split-bf16 MMA) ===============
__global__ __launch_bounds__(128) void outproj_mma(
    float* __restrict__ out, const float* __restrict__ Bv)
{
    __shared__ __align__(16) __nv_bfloat16 Ah[2][64][40], Al[2][64][40];
    __shared__ __align__(16) __nv_bfloat16 Bh[2][64][40], Bl[2][64][40];
    const int m0 = blockIdx.y * 64, n0 = blockIdx.x * 64;
    const int tid = threadIdx.x, wid = tid >> 5, ln = tid & 31;
    const int r0 = ln >> 2, c0 = (ln & 3) * 2;

    auto load_stage = [&](int s, int kt) {
#pragma unroll
        for (int p = 0; p < 2; p++) {
            int e = tid + p * 128, r = e >> 2, c = (e & 3) * 8;
            cp_async16(smaddr(&Ah[s][r][c]), &g_AOhi[(m0 + r) * 256 + kt + c]);
            cp_async16(smaddr(&Al[s][r][c]), &g_AOlo[(m0 + r) * 256 + kt + c]);
            cp_async16(smaddr(&Bh[s][r][c]), &g_Wothi[(n0 + r) * 256 + kt + c]);
            cp_async16(smaddr(&Bl[s][r][c]), &g_Wotlo[(n0 + r) * 256 + kt + c]);
        }
    };

    float s[8][4];
#pragma unroll
    for (int n = 0; n < 8; n++)
#pragma unroll
        for (int j = 0; j < 4; j++) s[n][j] = 0.0f;

    load_stage(0, 0); cp_commit();

    for (int it = 0; it < 8; it++) {
        const int buf = it & 1;
        cp_wait<0>();
        __syncthreads();
        if (it + 1 < 8) { load_stage(buf ^ 1, (it + 1) * 32); cp_commit(); }

#pragma unroll
        for (int kc = 0; kc < 2; kc++) {
            uint32_t ah[4], al[4];
            ah[0] = *(const uint32_t*)&Ah[buf][wid * 16 + r0][kc * 16 + c0];
            ah[1] = *(const uint32_t*)&Ah[buf][wid * 16 + r0 + 8][kc * 16 + c0];
            ah[2] = *(const uint32_t*)&Ah[buf][wid * 16 + r0][kc * 16 + c0 + 8];
            ah[3] = *(const uint32_t*)&Ah[buf][wid * 16 + r0 + 8][kc * 16 + c0 + 8];
            al[0] = *(const uint32_t*)&Al[buf][wid * 16 + r0][kc * 16 + c0];
            al[1] = *(const uint32_t*)&Al[buf][wid * 16 + r0 + 8][kc * 16 + c0];
            al[2] = *(const uint32_t*)&Al[buf][wid * 16 + r0][kc * 16 + c0 + 8];
            al[3] = *(const uint32_t*)&Al[buf][wid * 16 + r0 + 8][kc * 16 + c0 + 8];
#pragma unroll
            for (int n = 0; n < 8; n++) {
                uint32_t bh0 = *(const uint32_t*)&Bh[buf][n * 8 + r0][kc * 16 + c0];
                uint32_t bh1 = *(const uint32_t*)&Bh[buf][n * 8 + r0][kc * 16 + c0 + 8];
                uint32_t bl0 = *(const uint32_t*)&Bl[buf][n * 8 + r0][kc * 16 + c0];
                uint32_t bl1 = *(const uint32_t*)&Bl[buf][n * 8 + r0][kc * 16 + c0 + 8];
                mma_bf16(s[n], ah, bh0, bh1);
                mma_bf16(s[n], ah, bl0, bl1);
                mma_bf16(s[n], al, bh0, bh1);
            }
        }
    }

#pragma unroll
    for (int n = 0; n < 8; n++) {
#pragma unroll
        for (int half = 0; half < 2; half++) {
            int row = m0 + wid * 16 + r0 + half * 8;
            int col = n0 + n * 8 + c0;
            float2 v = { s[n][half * 2 + 0] + Bv[col], s[n][half * 2 + 1] + Bv[col + 1] };
            *(float2*)&out[row * 256 + col] = v;
        }
    }
}

// =============== launch ===============
extern "C" void kernel_launch(void* const* d_in, const int* in_sizes, int n_in,
                              void* d_out, int out_size) {
    const float* q_inputs   = (const float*)d_in[0];
    const float* kv_inputs  = (const float*)d_in[1];
    const float* bias       = (const float*)d_in[2];
    const float* qg_weights = (const float*)d_in[3];
    const float* kv_weights = (const float*)d_in[4];
    const float* qg_bias    = (const float*)d_in[5];
    const float* kv_bias    = (const float*)d_in[6];
    const float* o_weights  = (const float*)d_in[7];
    const float* o_bias     = (const float*)d_in[8];
    float* out = (float*)d_out;

    cudaFuncSetAttribute(attn_kernel, cudaFuncAttributeMaxDynamicSharedMemorySize, ATTN_SMEM);

    split_kernel<<<5376, 256>>>(q_inputs, kv_inputs, qg_weights, kv_weights, o_weights);
    proj_mma<<<dim3(8, 32, 2), 128>>>(qg_bias, kv_bias);
    attn_kernel<<<dim3(32, 8, NSPLIT), 128, ATTN_SMEM>>>(bias);
    merge_kernel<<<512, 256>>>();
    outproj_mma<<<dim3(4, 32), 128>>>(out, o_bias);
}

// round 13
// speedup vs baseline: 2.4592x; 1.0217x over previous
#include <cuda_runtime.h>
#include <cuda_bf16.h>
#include <cuda_fp16.h>
#include <stdint.h>

#define NHEAD 8
#define SLEN 2048
#define NSPLIT 2
#define SCALE 0.17677669529663689f
#define LOG2E 1.4426950408889634f

// ------------- device scratch (no allocation allowed) -------------
static __device__ __align__(16) __half g_Qh[NHEAD][SLEN][32];
static __device__ __align__(16) __half g_Kh[NHEAD][SLEN][32];
static __device__ __align__(16) __half g_Vth[NHEAD][32][SLEN];
static __device__ __align__(16) float g_G[NHEAD][SLEN][32];
static __device__ __align__(16) float g_Opart[NSPLIT][NHEAD][SLEN][32];
static __device__ __align__(16) float g_ml[NSPLIT][NHEAD][SLEN][2];
// split-bf16 inputs for MMA projections
static __device__ __align__(16) __nv_bfloat16 g_Xqhi[SLEN * 256], g_Xqlo[SLEN * 256];
static __device__ __align__(16) __nv_bfloat16 g_Xkhi[SLEN * 256], g_Xklo[SLEN * 256];
static __device__ __align__(16) __nv_bfloat16 g_Wqthi[512 * 256], g_Wqtlo[512 * 256];
static __device__ __align__(16) __nv_bfloat16 g_Wkthi[512 * 256], g_Wktlo[512 * 256];
static __device__ __align__(16) __nv_bfloat16 g_Wothi[256 * 256], g_Wotlo[256 * 256];
static __device__ __align__(16) __nv_bfloat16 g_AOhi[SLEN * 256], g_AOlo[SLEN * 256];

// ------------- helpers -------------
__device__ __forceinline__ float ex2f(float x) {
    float y; asm("ex2.approx.f32 %0, %1;" : "=f"(y) : "f"(x)); return y;
}
__device__ __forceinline__ uint32_t packbf(float lo, float hi) {
    uint32_t r; asm("cvt.rn.bf16x2.f32 %0, %1, %2;" : "=r"(r) : "f"(hi), "f"(lo)); return r;
}
__device__ __forceinline__ uint32_t packh(float lo, float hi) {
    uint32_t r; asm("cvt.rn.f16x2.f32 %0, %1, %2;" : "=r"(r) : "f"(hi), "f"(lo)); return r;
}
__device__ __forceinline__ void splitp(float x, float y, uint32_t &hi, uint32_t &lo) {
    hi = packbf(x, y);
    float xh = __uint_as_float(hi << 16);
    float yh = __uint_as_float(hi & 0xffff0000u);
    lo = packbf(x - xh, y - yh);
}
__device__ __forceinline__ void mma_bf16(float* d, const uint32_t* a, uint32_t b0, uint32_t b1) {
    asm volatile("mma.sync.aligned.m16n8k16.row.col.f32.bf16.bf16.f32 "
        "{%0,%1,%2,%3},{%4,%5,%6,%7},{%8,%9},{%0,%1,%2,%3};"
        : "+f"(d[0]), "+f"(d[1]), "+f"(d[2]), "+f"(d[3])
        : "r"(a[0]), "r"(a[1]), "r"(a[2]), "r"(a[3]), "r"(b0), "r"(b1));
}
__device__ __forceinline__ void mma_f16(float* d, const uint32_t* a, uint32_t b0, uint32_t b1) {
    asm volatile("mma.sync.aligned.m16n8k16.row.col.f32.f16.f16.f32 "
        "{%0,%1,%2,%3},{%4,%5,%6,%7},{%8,%9},{%0,%1,%2,%3};"
        : "+f"(d[0]), "+f"(d[1]), "+f"(d[2]), "+f"(d[3])
        : "r"(a[0]), "r"(a[1]), "r"(a[2]), "r"(a[3]), "r"(b0), "r"(b1));
}
__device__ __forceinline__ uint32_t smaddr(const void* p) {
    return (uint32_t)__cvta_generic_to_shared(p);
}
__device__ __forceinline__ void ldsm4(uint32_t* r, const void* p) {
    uint32_t a = smaddr(p);
    asm volatile("ldmatrix.sync.aligned.m8n8.x4.shared.b16 {%0,%1,%2,%3},[%4];"
        : "=r"(r[0]), "=r"(r[1]), "=r"(r[2]), "=r"(r[3]) : "r"(a));
}
__device__ __forceinline__ void cp_async16(uint32_t s, const void* g) {
    asm volatile("cp.async.cg.shared.global [%0], [%1], 16;" :: "r"(s), "l"(g));
}
__device__ __forceinline__ void cp_commit() { asm volatile("cp.async.commit_group;"); }
template<int N> __device__ __forceinline__ void cp_wait() {
    asm volatile("cp.async.wait_group %0;" :: "n"(N));
}
__device__ __forceinline__ void split_store(float v, __nv_bfloat16* hi, __nv_bfloat16* lo) {
    __nv_bfloat16 h = __float2bfloat16(v);
    *hi = h;
    *lo = __float2bfloat16(v - __bfloat162float(h));
}

// =============== kernel 0: split/transposed-split prepass ===============
__global__ __launch_bounds__(256) void split_kernel(
    const float* __restrict__ Xq, const float* __restrict__ Xkv,
    const float* __restrict__ Wq, const float* __restrict__ Wk,
    const float* __restrict__ Wo)
{
    const int NX = SLEN * 256;     // 524288
    const int NW = 256 * 512;      // 131072
    const int NO = 256 * 256;      // 65536
    int i = blockIdx.x * 256 + threadIdx.x;
    if (i < NX) {
        split_store(Xq[i], &g_Xqhi[i], &g_Xqlo[i]);
    } else if (i < 2 * NX) {
        int j = i - NX;
        split_store(Xkv[j], &g_Xkhi[j], &g_Xklo[j]);
    } else if (i < 2 * NX + NW) {
        int j = i - 2 * NX;                 // j = n*256 + k
        int n = j >> 8, k = j & 255;
        split_store(Wq[k * 512 + n], &g_Wqthi[j], &g_Wqtlo[j]);
    } else if (i < 2 * NX + 2 * NW) {
        int j = i - 2 * NX - NW;
        int n = j >> 8, k = j & 255;
        split_store(Wk[k * 512 + n], &g_Wkthi[j], &g_Wktlo[j]);
    } else {
        int j = i - 2 * NX - 2 * NW;
        if (j < NO) {
            int n = j >> 8, k = j & 255;
            split_store(Wo[k * 256 + n], &g_Wothi[j], &g_Wotlo[j]);
        }
    }
}

// =============== kernel 1: input projections (split-bf16 MMA) ===============
__global__ __launch_bounds__(128) void proj_mma(
    const float* __restrict__ Bq, const float* __restrict__ Bk)
{
    __shared__ __align__(16) __nv_bfloat16 Ah[2][64][40], Al[2][64][40];
    __shared__ __align__(16) __nv_bfloat16 Bh[2][64][40], Bl[2][64][40];
    const int z = blockIdx.z;
    const __nv_bfloat16* __restrict__ Xhi  = z ? g_Xkhi  : g_Xqhi;
    const __nv_bfloat16* __restrict__ Xlo  = z ? g_Xklo  : g_Xqlo;
    const __nv_bfloat16* __restrict__ Wthi = z ? g_Wkthi : g_Wqthi;
    const __nv_bfloat16* __restrict__ Wtlo = z ? g_Wktlo : g_Wqtlo;
    const float* __restrict__ Bv = z ? Bk : Bq;
    const int m0 = blockIdx.y * 64, n0 = blockIdx.x * 64;
    const int tid = threadIdx.x, wid = tid >> 5, ln = tid & 31;
    const int r0 = ln >> 2, c0 = (ln & 3) * 2;

    auto load_stage = [&](int s, int kt) {
#pragma unroll
        for (int p = 0; p < 2; p++) {
            int e = tid + p * 128, r = e >> 2, c = (e & 3) * 8;
            cp_async16(smaddr(&Ah[s][r][c]), &Xhi[(m0 + r) * 256 + kt + c]);
            cp_async16(smaddr(&Al[s][r][c]), &Xlo[(m0 + r) * 256 + kt + c]);
            cp_async16(smaddr(&Bh[s][r][c]), &Wthi[(n0 + r) * 256 + kt + c]);
            cp_async16(smaddr(&Bl[s][r][c]), &Wtlo[(n0 + r) * 256 + kt + c]);
        }
    };

    float s[8][4];
#pragma unroll
    for (int n = 0; n < 8; n++)
#pragma unroll
        for (int j = 0; j < 4; j++) s[n][j] = 0.0f;

    load_stage(0, 0); cp_commit();

    for (int it = 0; it < 8; it++) {
        const int buf = it & 1;
        cp_wait<0>();
        __syncthreads();
        if (it + 1 < 8) { load_stage(buf ^ 1, (it + 1) * 32); cp_commit(); }

#pragma unroll
        for (int kc = 0; kc < 2; kc++) {
            uint32_t ah[4], al[4];
            ah[0] = *(const uint32_t*)&Ah[buf][wid * 16 + r0][kc * 16 + c0];
            ah[1] = *(const uint32_t*)&Ah[buf][wid * 16 + r0 + 8][kc * 16 + c0];
            ah[2] = *(const uint32_t*)&Ah[buf][wid * 16 + r0][kc * 16 + c0 + 8];
            ah[3] = *(const uint32_t*)&Ah[buf][wid * 16 + r0 + 8][kc * 16 + c0 + 8];
            al[0] = *(const uint32_t*)&Al[buf][wid * 16 + r0][kc * 16 + c0];
            al[1] = *(const uint32_t*)&Al[buf][wid * 16 + r0 + 8][kc * 16 + c0];
            al[2] = *(const uint32_t*)&Al[buf][wid * 16 + r0][kc * 16 + c0 + 8];
            al[3] = *(const uint32_t*)&Al[buf][wid * 16 + r0 + 8][kc * 16 + c0 + 8];
#pragma unroll
            for (int n = 0; n < 8; n++) {
                uint32_t bh0 = *(const uint32_t*)&Bh[buf][n * 8 + r0][kc * 16 + c0];
                uint32_t bh1 = *(const uint32_t*)&Bh[buf][n * 8 + r0][kc * 16 + c0 + 8];
                uint32_t bl0 = *(const uint32_t*)&Bl[buf][n * 8 + r0][kc * 16 + c0];
                uint32_t bl1 = *(const uint32_t*)&Bl[buf][n * 8 + r0][kc * 16 + c0 + 8];
                mma_bf16(s[n], ah, bh0, bh1);
                mma_bf16(s[n], ah, bl0, bl1);
                mma_bf16(s[n], al, bh0, bh1);
            }
        }
    }

    // epilogue: write Q (fp16), K (fp16), V (fp16, transposed), G (fp32)
#pragma unroll
    for (int n = 0; n < 8; n++) {
#pragma unroll
        for (int j = 0; j < 4; j++) {
            int row = m0 + wid * 16 + r0 + (j >> 1) * 8;
            int col = n0 + n * 8 + c0 + (j & 1);
            float x = s[n][j] + Bv[col];
            int h = col >> 6, cc = col & 63;
            if (z == 0) {
                if (cc < 32) {
                    g_Qh[h][row][cc] = __float2half(x * SCALE);
                } else {
                    g_G[h][row][cc - 32] = 1.0f / (1.0f + __expf(-x));
                }
            } else {
                if (cc < 32) {
                    g_Kh[h][row][cc] = __float2half(x);
                } else {
                    g_Vth[h][cc - 32][row] = __float2half(x);
                }
            }
        }
    }
}

// =============== kernel 2: flash attention (fp16 MMA), split-K x2, full pipeline ===============
// dynamic smem layout (bytes):
//   Kh: 2 stages x 64x40 half  @ 0       (10240)
//   Vh: 2 stages x 32x72 half  @ 10240   (9216)
//   Bias: 2 stages x 64x68 f32 @ 19456   (34816)   total = 54272
#define ATTN_SMEM 54272
__global__ __launch_bounds__(128, 4) void attn_kernel(const float* __restrict__ bias)
{
    extern __shared__ __align__(16) char dynsm[];
    __half (*KhS)[64][40] = (__half(*)[64][40])(dynsm);
    __half (*VhS)[32][72] = (__half(*)[32][72])(dynsm + 10240);
    float* biasS = (float*)(dynsm + 19456);
#define BIASS(s, r, c) biasS[((s) * 64 + (r)) * 68 + (c)]

    const int h = blockIdx.y;
    const int z = blockIdx.z;
    const int tid = threadIdx.x, wid = tid >> 5, ln = tid & 31;
    const int q0b = blockIdx.x * 64;
    const int q0 = q0b + wid * 16;
    const int r0 = ln >> 2, c0 = (ln & 3) * 2;
    const int lr8 = ln & 7, lm = ln >> 3;   // ldmatrix addressing

    // one commit group = KV(stage) + bias(stage) for one iteration
    auto load_stage_kvb = [&](int s, int kt) {
#pragma unroll
        for (int p = 0; p < 2; p++) {
            int e = tid + p * 128, r = e >> 2, c = (e & 3) * 8;   // 8 halves = 16B
            cp_async16(smaddr(&KhS[s][r][c]), &g_Kh[h][kt + r][c]);
        }
#pragma unroll
        for (int p = 0; p < 2; p++) {
            int e = tid + p * 128, r = e >> 3, c = (e & 7) * 8;   // 8 halves = 16B
            cp_async16(smaddr(&VhS[s][r][c]), &g_Vth[h][r][kt + c]);
        }
#pragma unroll
        for (int p = 0; p < 8; p++) {
            int e = tid + p * 128, r = e >> 4, seg = e & 15;
            cp_async16(smaddr(&BIASS(s, r, seg * 4)),
                       &bias[(size_t)(h * SLEN + q0b + r) * SLEN + kt + seg * 4]);
        }
        cp_commit();
    };

    // Q fragments (single fp16), 2 k-chunks of 16
    uint32_t qh[2][4];
#pragma unroll
    for (int kc = 0; kc < 2; kc++) {
        qh[kc][0] = *(const uint32_t*)&g_Qh[h][q0 + r0][kc * 16 + c0];
        qh[kc][1] = *(const uint32_t*)&g_Qh[h][q0 + r0 + 8][kc * 16 + c0];
        qh[kc][2] = *(const uint32_t*)&g_Qh[h][q0 + r0][kc * 16 + c0 + 8];
        qh[kc][3] = *(const uint32_t*)&g_Qh[h][q0 + r0 + 8][kc * 16 + c0 + 8];
    }

    float o[4][4];
#pragma unroll
    for (int n = 0; n < 4; n++)
#pragma unroll
        for (int j = 0; j < 4; j++) o[n][j] = 0.0f;
    float mr[2] = { -1e30f, -1e30f };
    float lr[2] = { 0.0f, 0.0f };

    const int NIT = SLEN / 64 / NSPLIT;   // 16
    const int kstep = NSPLIT * 64;
    // prologue: two stages in flight
    load_stage_kvb(0, z * 64);
    load_stage_kvb(1, z * 64 + kstep);

    for (int it = 0; it < NIT; it++) {
        const int kt = it * kstep + z * 64;
        const int buf = it & 1;
        if (it + 1 < NIT) cp_wait<1>(); else cp_wait<0>();
        __syncthreads();

        // S = Q K^T  (single fp16 both sides, 2 MMAs per n-tile)
        float s[8][4];
#pragma unroll
        for (int n = 0; n < 8; n++) {
            s[n][0] = s[n][1] = s[n][2] = s[n][3] = 0.0f;
            uint32_t kh[4];
            ldsm4(kh, &KhS[buf][n * 8 + lr8][lm * 8]);
            mma_f16(s[n], qh[0], kh[0], kh[1]);
            mma_f16(s[n], qh[1], kh[2], kh[3]);
        }
        float mx[2] = { -1e30f, -1e30f };
        const int br0 = wid * 16 + r0;
#pragma unroll
        for (int n = 0; n < 8; n++) {
            float2 b0 = *(const float2*)&BIASS(buf, br0, n * 8 + c0);
            float2 b1 = *(const float2*)&BIASS(buf, br0 + 8, n * 8 + c0);
            s[n][0] += b0.x; s[n][1] += b0.y;
            s[n][2] += b1.x; s[n][3] += b1.y;
            mx[0] = fmaxf(mx[0], fmaxf(s[n][0], s[n][1]));
            mx[1] = fmaxf(mx[1], fmaxf(s[n][2], s[n][3]));
        }
#pragma unroll
        for (int i = 0; i < 2; i++) {
            mx[i] = fmaxf(mx[i], __shfl_xor_sync(0xffffffffu, mx[i], 1));
            mx[i] = fmaxf(mx[i], __shfl_xor_sync(0xffffffffu, mx[i], 2));
        }
        float mn[2] = { fmaxf(mr[0], mx[0]), fmaxf(mr[1], mx[1]) };
        float rs[2] = { ex2f((mr[0] - mn[0]) * LOG2E), ex2f((mr[1] - mn[1]) * LOG2E) };
        mr[0] = mn[0]; mr[1] = mn[1];
#pragma unroll
        for (int n = 0; n < 4; n++) {
            o[n][0] *= rs[0]; o[n][1] *= rs[0]; o[n][2] *= rs[1]; o[n][3] *= rs[1];
        }
        float sm[2] = { 0.0f, 0.0f };
#pragma unroll
        for (int n = 0; n < 8; n++)
#pragma unroll
            for (int j = 0; j < 4; j++) {
                float p = ex2f((s[n][j] - mn[j >> 1]) * LOG2E);
                s[n][j] = p;
                sm[j >> 1] += p;
            }
#pragma unroll
        for (int i = 0; i < 2; i++) {
            sm[i] += __shfl_xor_sync(0xffffffffu, sm[i], 1);
            sm[i] += __shfl_xor_sync(0xffffffffu, sm[i], 2);
            lr[i] = lr[i] * rs[i] + sm[i];
        }
        // pack P into single fp16 A-fragments
        uint32_t ph[4][4];
#pragma unroll
        for (int kc = 0; kc < 4; kc++) {
            ph[kc][0] = packh(s[2 * kc][0],     s[2 * kc][1]);
            ph[kc][1] = packh(s[2 * kc][2],     s[2 * kc][3]);
            ph[kc][2] = packh(s[2 * kc + 1][0], s[2 * kc + 1][1]);
            ph[kc][3] = packh(s[2 * kc + 1][2], s[2 * kc + 1][3]);
        }
        // O += P V  (single fp16 V, 4 MMAs per n-tile)
#pragma unroll
        for (int n = 0; n < 4; n++) {
            uint32_t vh[8];
            ldsm4(vh,     &VhS[buf][n * 8 + lr8][lm * 8]);
            ldsm4(vh + 4, &VhS[buf][n * 8 + lr8][32 + lm * 8]);
#pragma unroll
            for (int kc = 0; kc < 4; kc++) {
                mma_f16(o[n], ph[kc], vh[kc * 2], vh[kc * 2 + 1]);
            }
        }

        // refill this buffer for iteration it+2 (after all warps done reading)
        __syncthreads();
        if (it + 2 < NIT) load_stage_kvb(buf, kt + 2 * kstep);
    }
#pragma unroll
    for (int n = 0; n < 4; n++) {
        float2 w0 = { o[n][0], o[n][1] };
        float2 w1 = { o[n][2], o[n][3] };
        *(float2*)&g_Opart[z][h][q0 + r0][n * 8 + c0] = w0;
        *(float2*)&g_Opart[z][h][q0 + r0 + 8][n * 8 + c0] = w1;
    }
    if ((ln & 3) == 0) {
        g_ml[z][h][q0 + r0][0] = mr[0];
        g_ml[z][h][q0 + r0][1] = lr[0];
        g_ml[z][h][q0 + r0 + 8][0] = mr[1];
        g_ml[z][h][q0 + r0 + 8][1] = lr[1];
    }
#undef BIASS
}

// =============== kernel 2b: split-K merge + gate -> AO (bf16 split), coalesced ===============
__global__ __launch_bounds__(256) void merge_kernel()
{
    int t = blockIdx.x * 256 + threadIdx.x;   // 131072 threads: 8 per (h,q) row
    int ln = threadIdx.x & 31;
    int row = t >> 3, cs = (t & 7) * 4;
    int h = row >> 11, q = row & 2047;

    // lane-group (8 lanes share a row) leader loads m/l, broadcast via shfl
    float m0v = 0.f, l0v = 0.f, m1v = 0.f, l1v = 0.f;
    if ((ln & 7) == 0) {
        float2 a = *(const float2*)&g_ml[0][h][q][0];
        float2 b = *(const float2*)&g_ml[1][h][q][0];
        m0v = a.x; l0v = a.y; m1v = b.x; l1v = b.y;
    }
    int src = ln & ~7;
    m0v = __shfl_sync(0xffffffffu, m0v, src);
    l0v = __shfl_sync(0xffffffffu, l0v, src);
    m1v = __shfl_sync(0xffffffffu, m1v, src);
    l1v = __shfl_sync(0xffffffffu, l1v, src);

    float m = fmaxf(m0v, m1v);
    float a0 = ex2f((m0v - m) * LOG2E);
    float a1 = ex2f((m1v - m) * LOG2E);
    float rl = 1.0f / (l0v * a0 + l1v * a1);
    a0 *= rl; a1 *= rl;

    float4 x0 = *(const float4*)&g_Opart[0][h][q][cs];
    float4 x1 = *(const float4*)&g_Opart[1][h][q][cs];
    float4 gg = *(const float4*)&g_G[h][q][cs];
    float4 r;
    r.x = (x0.x * a0 + x1.x * a1) * gg.x;
    r.y = (x0.y * a0 + x1.y * a1) * gg.y;
    r.z = (x0.z * a0 + x1.z * a1) * gg.z;
    r.w = (x0.w * a0 + x1.w * a1) * gg.w;
    uint32_t h01, l01, h23, l23;
    splitp(r.x, r.y, h01, l01);
    splitp(r.z, r.w, h23, l23);
    int base = q * 256 + h * 32 + cs;
    *(uint2*)&g_AOhi[base] = make_uint2(h01, h23);
    *(uint2*)&g_AOlo[base] = make_uint2(l01, l23);
}

// =============== kernel 3: output projection (split-bf16 MMA) ===============
__global__ __launch_bounds__(128) void outproj_mma(
    float* __restrict__ out, const float* __restrict__ Bv)
{
    __shared__ __align__(16) __nv_bfloat16 Ah[2][64][40], Al[2][64][40];
    __shared__ __align__(16) __nv_bfloat16 Bh[2][64][40], Bl[2][64][40];
    const int m0 = blockIdx.y * 64, n0 = blockIdx.x * 64;
    const int tid = threadIdx.x, wid = tid >> 5, ln = tid & 31;
    const int r0 = ln >> 2, c0 = (ln & 3) * 2;

    auto load_stage = [&](int s, int kt) {
#pragma unroll
        for (int p = 0; p < 2; p++) {
            int e = tid + p * 128, r = e >> 2, c = (e & 3) * 8;
            cp_async16(smaddr(&Ah[s][r][c]), &g_AOhi[(m0 + r) * 256 + kt + c]);
            cp_async16(smaddr(&Al[s][r][c]), &g_AOlo[(m0 + r) * 256 + kt + c]);
            cp_async16(smaddr(&Bh[s][r][c]), &g_Wothi[(n0 + r) * 256 + kt + c]);
            cp_async16(smaddr(&Bl[s][r][c]), &g_Wotlo[(n0 + r) * 256 + kt + c]);
        }
    };

    float s[8][4];
#pragma unroll
    for (int n = 0; n < 8; n++)
#pragma unroll
        for (int j = 0; j < 4; j++) s[n][j] = 0.0f;

    load_stage(0, 0); cp_commit();

    for (int it = 0; it < 8; it++) {
        const int buf = it & 1;
        cp_wait<0>();
        __syncthreads();
        if (it + 1 < 8) { load_stage(buf ^ 1, (it + 1) * 32); cp_commit(); }

#pragma unroll
        for (int kc = 0; kc < 2; kc++) {
            uint32_t ah[4], al[4];
            ah[0] = *(const uint32_t*)&Ah[buf][wid * 16 + r0][kc * 16 + c0];
            ah[1] = *(const uint32_t*)&Ah[buf][wid * 16 + r0 + 8][kc * 16 + c0];
            ah[2] = *(const uint32_t*)&Ah[buf][wid * 16 + r0][kc * 16 + c0 + 8];
            ah[3] = *(const uint32_t*)&Ah[buf][wid * 16 + r0 + 8][kc * 16 + c0 + 8];
            al[0] = *(const uint32_t*)&Al[buf][wid * 16 + r0][kc * 16 + c0];
            al[1] = *(const uint32_t*)&Al[buf][wid * 16 + r0 + 8][kc * 16 + c0];
            al[2] = *(const uint32_t*)&Al[buf][wid * 16 + r0][kc * 16 + c0 + 8];
            al[3] = *(const uint32_t*)&Al[buf][wid * 16 + r0 + 8][kc * 16 + c0 + 8];
#pragma unroll
            for (int n = 0; n < 8; n++) {
                uint32_t bh0 = *(const uint32_t*)&Bh[buf][n * 8 + r0][kc * 16 + c0];
                uint32_t bh1 = *(const uint32_t*)&Bh[buf][n * 8 + r0][kc * 16 + c0 + 8];
                uint32_t bl0 = *(const uint32_t*)&Bl[buf][n * 8 + r0][kc * 16 + c0];
                uint32_t bl1 = *(const uint32_t*)&Bl[buf][n * 8 + r0][kc * 16 + c0 + 8];
                mma_bf16(s[n], ah, bh0, bh1);
                mma_bf16(s[n], ah, bl0, bl1);
                mma_bf16(s[n], al, bh0, bh1);
            }
        }
    }

#pragma unroll
    for (int n = 0; n < 8; n++) {
#pragma unroll
        for (int half = 0; half < 2; half++) {
            int row = m0 + wid * 16 + r0 + half * 8;
            int col = n0 + n * 8 + c0;
            float2 v = { s[n][half * 2 + 0] + Bv[col], s[n][half * 2 + 1] + Bv[col + 1] };
            *(float2*)&out[row * 256 + col] = v;
        }
    }
}

// =============== launch ===============
extern "C" void kernel_launch(void* const* d_in, const int* in_sizes, int n_in,
                              void* d_out, int out_size) {
    const float* q_inputs   = (const float*)d_in[0];
    const float* kv_inputs  = (const float*)d_in[1];
    const float* bias       = (const float*)d_in[2];
    const float* qg_weights = (const float*)d_in[3];
    const float* kv_weights = (const float*)d_in[4];
    const float* qg_bias    = (const float*)d_in[5];
    const float* kv_bias    = (const float*)d_in[6];
    const float* o_weights  = (const float*)d_in[7];
    const float* o_bias     = (const float*)d_in[8];
    float* out = (float*)d_out;

    cudaFuncSetAttribute(attn_kernel, cudaFuncAttributeMaxDynamicSharedMemorySize, ATTN_SMEM);

    split_kernel<<<5376, 256>>>(q_inputs, kv_inputs, qg_weights, kv_weights, o_weights);
    proj_mma<<<dim3(8, 32, 2), 128>>>(qg_bias, kv_bias);
    attn_kernel<<<dim3(32, 8, NSPLIT), 128, ATTN_SMEM>>>(bias);
    merge_kernel<<<512, 256>>>();
    outproj_mma<<<dim3(4, 32), 128>>>(out, o_bias);
}